// round 10
// baseline (speedup 1.0000x reference)
#include <cuda_runtime.h>
#include <cuda_bf16.h>
#include <cstdint>

#define BB   64
#define TT_  64
#define GG   11
#define FF   4
#define HH   256
#define EE   128
#define NT   3
#define GT   (GG*BB)     // 704
#define MTOT (TT_*GT)    // 45056
#define NG   1024

// encoder tc persistent tile
#define ER 64
#define EC 128
#define BP 132
#define AP 132
#define SB_WORDS (2*128*BP)
#define SA_WORDS (2*64*AP)
#define SMEM_ENC ((SB_WORDS + SA_WORDS)*4)  // 202752 B

// decoder tc persistent tile
#define DNB 48
#define DKP 132
#define DW_WORDS (2*64*DKP)
#define SMEM_DEC (2*DW_WORDS*4)            // 135168 B

__device__ float g_X[MTOT*NG];
__device__ float g_Y0[MTOT*HH];
__device__ float g_Cst[GT*HH];
__device__ __nv_bfloat16 g_Ahi[MTOT*HH];
__device__ __nv_bfloat16 g_Alo[MTOT*HH];
__device__ __nv_bfloat16 g_WihHi[(EE + 3*HH)*NG];
__device__ __nv_bfloat16 g_WihLo[(EE + 3*HH)*NG];
__device__ __nv_bfloat16 g_WhhHi[4*NG*HH];
__device__ __nv_bfloat16 g_WhhLo[4*NG*HH];
__device__ float g_biasEncP[4*NG];
__device__ float g_decWhhT[3*HH*NG];
__device__ float g_WcPack[512*NG];
__device__ float g_biasDec[4*NG];
__device__ float g_dech[4*BB*HH];
__device__ float g_decc[4*BB*HH];
__device__ float g_attn[BB*HH];
__device__ float g_cin[BB*512];
__device__ float g_const[4*BB*NG];
__device__ float g_constP[4*BB*NG];
__device__ __nv_bfloat16 g_dWHi[(EE + 3*HH)*NG];
__device__ __nv_bfloat16 g_dWLo[(EE + 3*HH)*NG];
__device__ __nv_bfloat16 g_d1h[NT*BB*HH];
__device__ __nv_bfloat16 g_d1l[NT*BB*HH];
__device__ __nv_bfloat16 g_d2h[NT*BB*HH];
__device__ __nv_bfloat16 g_d2l[NT*BB*HH];
__device__ unsigned g_bcnt = 0;
__device__ unsigned g_flag = 0;

__device__ __forceinline__ float fsig(float x){ return 1.f/(1.f + __expf(-x)); }
__device__ __forceinline__ float ftanh(float x){ return 1.f - 2.f/(__expf(2.f*x) + 1.f); }

__device__ __host__ __forceinline__ int permn(int n)
{
    int gate = n >> 8, h = n & 255;
    return (h >> 1)*8 + gate*2 + (h & 1);
}

__global__ void reset_barrier_k(){ g_bcnt = 0; g_flag = 0; }

__device__ __forceinline__ void grid_barrier(unsigned nb, unsigned& round)
{
    __syncthreads();
    if (threadIdx.x == 0){
        unsigned target = ++round;
        __threadfence();
        unsigned old = atomicAdd(&g_bcnt, 1u);
        if (old == target*nb - 1u){
            asm volatile("st.release.gpu.global.u32 [%0], %1;"
                         :: "l"(&g_flag), "r"(target) : "memory");
            __threadfence();
        } else {
            unsigned v;
            while (true){
                asm volatile("ld.acquire.gpu.global.u32 %0, [%1];"
                             : "=r"(v) : "l"(&g_flag) : "memory");
                if (v >= target) break;
                __nanosleep(32);
            }
        }
    }
    __syncthreads();
}

__global__ void transpose_k(const float* __restrict__ src, int ldS, int rows, int cols,
                            float* __restrict__ dst, int ldD)
{
    __shared__ float tile[32][33];
    int c0 = blockIdx.x*32, r0 = blockIdx.y*32;
    for (int i = threadIdx.y; i < 32; i += 8){
        int r = r0 + i, c = c0 + threadIdx.x;
        tile[i][threadIdx.x] = (r < rows && c < cols) ? src[(size_t)r*ldS + c] : 0.f;
    }
    __syncthreads();
    for (int i = threadIdx.y; i < 32; i += 8){
        int c = c0 + i, r = r0 + threadIdx.x;
        if (c < cols && r < rows) dst[(size_t)c*ldD + r] = tile[threadIdx.x][i];
    }
}

__global__ void addv_k(const float* a, const float* b, float* o, int n)
{
    int i = blockIdx.x*256 + threadIdx.x;
    if (i < n) o[i] = a[i] + b[i];
}

__global__ void addv_perm_k(const float* __restrict__ a, const float* __restrict__ b,
                            float* __restrict__ o)
{
    int n = blockIdx.x*256 + threadIdx.x;
    if (n < NG) o[permn(n)] = a[n] + b[n];
}

__global__ void wsplit_perm_k(const float* __restrict__ src, int K,
                              __nv_bfloat16* __restrict__ hi, __nv_bfloat16* __restrict__ lo)
{
    int i = blockIdx.x*256 + threadIdx.x;
    if (i < NG*K){
        int n = i / K, k = i - n*K;
        float v = src[i];
        __nv_bfloat16 h = __float2bfloat16(v);
        int d = permn(n)*K + k;
        hi[d] = h;
        lo[d] = __float2bfloat16(v - __bfloat162float(h));
    }
}

// strided variant: src row stride ldS, column offset koff
__global__ void wsplit_perm2_k(const float* __restrict__ src, int ldS, int koff, int K,
                               __nv_bfloat16* __restrict__ hi, __nv_bfloat16* __restrict__ lo)
{
    int i = blockIdx.x*256 + threadIdx.x;
    if (i < NG*K){
        int n = i / K, k = i - n*K;
        float v = src[(size_t)n*ldS + koff + k];
        __nv_bfloat16 h = __float2bfloat16(v);
        int d = permn(n)*K + k;
        hi[d] = h;
        lo[d] = __float2bfloat16(v - __bfloat162float(h));
    }
}

__global__ void perm_const_k(const float* __restrict__ src, float* __restrict__ dst)
{
    int i = blockIdx.x*256 + threadIdx.x;
    if (i < 4*BB*NG){
        int lb = i >> 10, n = i & 1023;
        dst[(lb << 10) + permn(n)] = src[i];
    }
}

__global__ void emb_k(const float* __restrict__ x, const float* __restrict__ W,
                      const float* __restrict__ bias,
                      __nv_bfloat16* __restrict__ hi, __nv_bfloat16* __restrict__ lo)
{
    int m = blockIdx.x;
    int t = m / GT; int rem = m % GT; int g = rem >> 6; int b = rem & 63;
    const float* xr = x + (((size_t)(b*TT_ + t))*GG + g)*FF;
    int e = threadIdx.x;
    float v = bias[e] + xr[0]*W[e*4] + xr[1]*W[e*4+1] + xr[2]*W[e*4+2] + xr[3]*W[e*4+3];
    v = fmaxf(v, 0.f);
    __nv_bfloat16 h = __float2bfloat16(v);
    hi[(size_t)m*EE + e] = h;
    lo[(size_t)m*EE + e] = __float2bfloat16(v - __bfloat162float(h));
}

__device__ __forceinline__ void mma_bf16(float* c, const uint32_t* a, uint32_t b0, uint32_t b1)
{
    asm volatile("mma.sync.aligned.m16n8k16.row.col.f32.bf16.bf16.f32 "
        "{%0,%1,%2,%3}, {%4,%5,%6,%7}, {%8,%9}, {%0,%1,%2,%3};"
        : "+f"(c[0]), "+f"(c[1]), "+f"(c[2]), "+f"(c[3])
        : "r"(a[0]), "r"(a[1]), "r"(a[2]), "r"(a[3]), "r"(b0), "r"(b1));
}

// Tensor-core split-bf16 GEMM: C[M][1024] = A[M][K] @ W[1024][K]^T + bias
__global__ __launch_bounds__(256, 2) void gemm_tc_k(
    const __nv_bfloat16* __restrict__ Ahi, const __nv_bfloat16* __restrict__ Alo,
    const __nv_bfloat16* __restrict__ Whi, const __nv_bfloat16* __restrict__ Wlo,
    const float* __restrict__ bias, float* __restrict__ C, int K)
{
    __shared__ __align__(16) uint32_t sA[2][128][20];
    __shared__ __align__(16) uint32_t sB[2][128][20];
    const int tid = threadIdx.x;
    const int lane = tid & 31, wid = tid >> 5;
    const int wm = wid & 3, wn = wid >> 2;
    const int m0 = blockIdx.y*128, n0 = blockIdx.x*128;
    const int g = lane >> 2, q = lane & 3;
    float acc[2][8][4];
    #pragma unroll
    for (int i = 0; i < 2; i++)
        #pragma unroll
        for (int j = 0; j < 8; j++){ acc[i][j][0]=0.f; acc[i][j][1]=0.f; acc[i][j][2]=0.f; acc[i][j][3]=0.f; }

    for (int k0 = 0; k0 < K; k0 += 32){
        #pragma unroll
        for (int rep = 0; rep < 2; rep++){
            int chunk = tid + rep*256;
            int row = chunk >> 2, off = chunk & 3;
            size_t ga = (size_t)(m0 + row)*K + k0 + off*8;
            size_t gb = (size_t)(n0 + row)*K + k0 + off*8;
            *reinterpret_cast<uint4*>(&sA[0][row][off*4]) = *reinterpret_cast<const uint4*>(Ahi + ga);
            *reinterpret_cast<uint4*>(&sA[1][row][off*4]) = *reinterpret_cast<const uint4*>(Alo + ga);
            *reinterpret_cast<uint4*>(&sB[0][row][off*4]) = *reinterpret_cast<const uint4*>(Whi + gb);
            *reinterpret_cast<uint4*>(&sB[1][row][off*4]) = *reinterpret_cast<const uint4*>(Wlo + gb);
        }
        __syncthreads();
        #pragma unroll
        for (int ks = 0; ks < 2; ks++){
            int kp = q + ks*8;
            uint32_t a[2][2][4];
            #pragma unroll
            for (int fm = 0; fm < 2; fm++){
                int row = wm*32 + fm*16;
                #pragma unroll
                for (int s = 0; s < 2; s++){
                    a[fm][s][0] = sA[s][row+g][kp];
                    a[fm][s][1] = sA[s][row+g+8][kp];
                    a[fm][s][2] = sA[s][row+g][kp+4];
                    a[fm][s][3] = sA[s][row+g+8][kp+4];
                }
            }
            #pragma unroll
            for (int fn = 0; fn < 8; fn++){
                int nr = wn*64 + fn*8 + g;
                uint32_t bh0 = sB[0][nr][kp], bh1 = sB[0][nr][kp+4];
                uint32_t bl0 = sB[1][nr][kp], bl1 = sB[1][nr][kp+4];
                #pragma unroll
                for (int fm = 0; fm < 2; fm++){
                    mma_bf16(acc[fm][fn], a[fm][0], bh0, bh1);
                    mma_bf16(acc[fm][fn], a[fm][0], bl0, bl1);
                    mma_bf16(acc[fm][fn], a[fm][1], bh0, bh1);
                }
            }
        }
        __syncthreads();
    }
    #pragma unroll
    for (int fm = 0; fm < 2; fm++){
        int r = m0 + wm*32 + fm*16 + g;
        #pragma unroll
        for (int fn = 0; fn < 8; fn++){
            int cn = n0 + wn*64 + fn*8 + q*2;
            float b0 = bias[cn], b1 = bias[cn+1];
            float2 v0 = make_float2(acc[fm][fn][0] + b0, acc[fm][fn][1] + b1);
            float2 v1 = make_float2(acc[fm][fn][2] + b0, acc[fm][fn][3] + b1);
            *reinterpret_cast<float2*>(C + (size_t)r*NG + cn) = v0;
            *reinterpret_cast<float2*>(C + (size_t)(r+8)*NG + cn) = v1;
        }
    }
}

// fp32 GEMM (decoder constants, small)
__global__ void gemm_k(const float* __restrict__ A, const float* __restrict__ B,
                       const float* __restrict__ bias, float* __restrict__ C,
                       int M, int N, int K)
{
    __shared__ float As[8][128];
    __shared__ float Bs[8][128];
    int tid = threadIdx.x;
    int m0 = blockIdx.y*128, n0 = blockIdx.x*128;
    int tx = tid & 15, ty = tid >> 4;
    float acc[8][8];
    #pragma unroll
    for (int i = 0; i < 8; i++)
        #pragma unroll
        for (int j = 0; j < 8; j++) acc[i][j] = 0.f;
    int arow = tid >> 1, acol = (tid & 1)*4;
    int brow = tid >> 5, bcol = (tid & 31)*4;
    for (int k0 = 0; k0 < K; k0 += 8){
        float4 av = make_float4(0.f,0.f,0.f,0.f);
        int gm = m0 + arow;
        if (gm < M) av = *reinterpret_cast<const float4*>(A + (size_t)gm*K + k0 + acol);
        As[acol+0][arow] = av.x; As[acol+1][arow] = av.y;
        As[acol+2][arow] = av.z; As[acol+3][arow] = av.w;
        *reinterpret_cast<float4*>(&Bs[brow][bcol]) =
            *reinterpret_cast<const float4*>(B + (size_t)(k0+brow)*N + n0 + bcol);
        __syncthreads();
        #pragma unroll
        for (int kk = 0; kk < 8; kk++){
            float a[8], b[8];
            *reinterpret_cast<float4*>(a)   = *reinterpret_cast<float4*>(&As[kk][ty*4]);
            *reinterpret_cast<float4*>(a+4) = *reinterpret_cast<float4*>(&As[kk][64+ty*4]);
            *reinterpret_cast<float4*>(b)   = *reinterpret_cast<float4*>(&Bs[kk][tx*4]);
            *reinterpret_cast<float4*>(b+4) = *reinterpret_cast<float4*>(&Bs[kk][64+tx*4]);
            #pragma unroll
            for (int i = 0; i < 8; i++)
                #pragma unroll
                for (int j = 0; j < 8; j++) acc[i][j] += a[i]*b[j];
        }
        __syncthreads();
    }
    #pragma unroll
    for (int i = 0; i < 8; i++){
        int gm = m0 + ((i < 4) ? (ty*4 + i) : (64 + ty*4 + (i-4)));
        if (gm >= M) continue;
        #pragma unroll
        for (int j = 0; j < 8; j++){
            int gn = n0 + ((j < 4) ? (tx*4 + j) : (64 + tx*4 + (j-4)));
            C[(size_t)gm*N + gn] = acc[i][j] + bias[gn];
        }
    }
}

// ---------------------------------------------------------------------------
// Persistent tensor-core encoder layer: 64 steps, one launch, 88 blocks.
// ---------------------------------------------------------------------------
extern __shared__ uint32_t sdyn[];

__global__ void __launch_bounds__(256, 1) enc_tc_k(
    const float* __restrict__ X,
    const __nv_bfloat16* __restrict__ WHi, const __nv_bfloat16* __restrict__ WLo,
    float* __restrict__ Y, float* __restrict__ Cfin,
    __nv_bfloat16* __restrict__ Hhi, __nv_bfloat16* __restrict__ Hlo)
{
    uint32_t* sB = sdyn;
    uint32_t* sA = sdyn + SB_WORDS;
    float* sG = reinterpret_cast<float*>(sA);
    const int tid = threadIdx.x;
    const int lane = tid & 31, wid = tid >> 5;
    const int wm = wid & 1, wn = wid >> 1;
    const int g = lane >> 2, q = lane & 3;
    const int rt = blockIdx.x % 11, ct = blockIdx.x / 11;
    const int m0 = rt*ER, n0 = ct*EC;
    const unsigned nb = gridDim.x;
    unsigned round = 0;

    for (int i = tid; i < 2*128*32; i += 256){
        int s = i >> 12;
        int rem = i & 4095;
        int row = rem >> 5, w4 = rem & 31;
        const uint4* src = reinterpret_cast<const uint4*>(
            (s ? WLo : WHi) + (size_t)(n0 + row)*HH) + w4;
        *reinterpret_cast<uint4*>(&sB[s*128*BP + row*BP + w4*4]) = *src;
    }
    __syncthreads();

    const int erow = tid >> 2;
    const int hb = (tid & 3)*8;
    float c[8];
    #pragma unroll
    for (int e = 0; e < 8; e++) c[e] = 0.f;

    for (int t = 0; t < 64; t++){
        if (t > 0){
            for (int i = tid; i < 2*64*32; i += 256){
                int s = i >> 11;
                int rem = i & 2047;
                int row = rem >> 5, w4 = rem & 31;
                const uint4* src = reinterpret_cast<const uint4*>(
                    (s ? Hlo : Hhi) + ((size_t)(t-1)*GT + m0 + row)*HH) + w4;
                uint4 v = __ldcg(src);
                *reinterpret_cast<uint4*>(&sA[s*64*AP + row*AP + w4*4]) = v;
            }
            __syncthreads();
            float acc[2][4][4];
            #pragma unroll
            for (int i = 0; i < 2; i++)
                #pragma unroll
                for (int j = 0; j < 4; j++){ acc[i][j][0]=0.f; acc[i][j][1]=0.f; acc[i][j][2]=0.f; acc[i][j][3]=0.f; }
            #pragma unroll
            for (int ks = 0; ks < 16; ks++){
                const int kp = ks*8 + q;
                uint32_t a[2][2][4];
                #pragma unroll
                for (int fm = 0; fm < 2; fm++){
                    int row = wm*32 + fm*16;
                    #pragma unroll
                    for (int s = 0; s < 2; s++){
                        const uint32_t* base = sA + s*64*AP;
                        a[fm][s][0] = base[(row+g)*AP + kp];
                        a[fm][s][1] = base[(row+g+8)*AP + kp];
                        a[fm][s][2] = base[(row+g)*AP + kp+4];
                        a[fm][s][3] = base[(row+g+8)*AP + kp+4];
                    }
                }
                #pragma unroll
                for (int fn = 0; fn < 4; fn++){
                    int nr = wn*32 + fn*8 + g;
                    uint32_t bh0 = sB[nr*BP + kp], bh1 = sB[nr*BP + kp+4];
                    uint32_t bl0 = sB[128*BP + nr*BP + kp], bl1 = sB[128*BP + nr*BP + kp+4];
                    #pragma unroll
                    for (int fm = 0; fm < 2; fm++){
                        mma_bf16(acc[fm][fn], a[fm][0], bh0, bh1);
                        mma_bf16(acc[fm][fn], a[fm][0], bl0, bl1);
                        mma_bf16(acc[fm][fn], a[fm][1], bh0, bh1);
                    }
                }
            }
            __syncthreads();
            #pragma unroll
            for (int fm = 0; fm < 2; fm++){
                int r1 = wm*32 + fm*16 + g;
                #pragma unroll
                for (int fn = 0; fn < 4; fn++){
                    int c0 = wn*32 + fn*8 + q*2;
                    *reinterpret_cast<float2*>(&sG[r1*AP + c0]) =
                        make_float2(acc[fm][fn][0], acc[fm][fn][1]);
                    *reinterpret_cast<float2*>(&sG[(r1+8)*AP + c0]) =
                        make_float2(acc[fm][fn][2], acc[fm][fn][3]);
                }
            }
            __syncthreads();
        }
        const float* xp = X + ((size_t)t*GT + m0 + erow)*NG + n0;
        const size_t yb = ((size_t)t*GT + m0 + erow)*HH + ct*32 + hb;
        #pragma unroll
        for (int ep = 0; ep < 4; ep++){
            int h2 = (hb >> 1) + ep;
            int cb = h2*8;
            float4 x0 = *reinterpret_cast<const float4*>(xp + cb);
            float4 x1 = *reinterpret_cast<const float4*>(xp + cb + 4);
            float gi0 = x0.x, gi1 = x0.y, gf0 = x0.z, gf1 = x0.w;
            float gg0 = x1.x, gg1 = x1.y, go0 = x1.z, go1 = x1.w;
            if (t > 0){
                float4 s0 = *reinterpret_cast<const float4*>(&sG[erow*AP + cb]);
                float4 s1 = *reinterpret_cast<const float4*>(&sG[erow*AP + cb + 4]);
                gi0 += s0.x; gi1 += s0.y; gf0 += s0.z; gf1 += s0.w;
                gg0 += s1.x; gg1 += s1.y; go0 += s1.z; go1 += s1.w;
            }
            float c0 = fsig(gf0)*c[ep*2]   + fsig(gi0)*ftanh(gg0);
            float c1 = fsig(gf1)*c[ep*2+1] + fsig(gi1)*ftanh(gg1);
            c[ep*2] = c0; c[ep*2+1] = c1;
            float h0 = fsig(go0)*ftanh(c0);
            float h1 = fsig(go1)*ftanh(c1);
            *reinterpret_cast<float2*>(Y + yb + 2*ep) = make_float2(h0, h1);
            __nv_bfloat16 b0 = __float2bfloat16(h0), b1 = __float2bfloat16(h1);
            __nv_bfloat162 hhv; hhv.x = b0; hhv.y = b1;
            __nv_bfloat162 llv;
            llv.x = __float2bfloat16(h0 - __bfloat162float(b0));
            llv.y = __float2bfloat16(h1 - __bfloat162float(b1));
            *reinterpret_cast<__nv_bfloat162*>(Hhi + yb + 2*ep) = hhv;
            *reinterpret_cast<__nv_bfloat162*>(Hlo + yb + 2*ep) = llv;
        }
        grid_barrier(nb, round);
    }
    const size_t cbse = (size_t)(m0 + erow)*HH + ct*32 + hb;
    #pragma unroll
    for (int e = 0; e < 8; e++) Cfin[cbse + 2*(e>>1) + (e&1)] = c[e];
}

__global__ void snap_k(const float* __restrict__ Yt, const float* __restrict__ C,
                       const int* __restrict__ tord, float* dh, float* dc)
{
    int b = blockIdx.x, h = threadIdx.x;
    int row = (*tord)*64 + b;
    dh[b*HH + h] = Yt[(size_t)row*HH + h];
    dc[b*HH + h] = C[(size_t)row*HH + h];
}

__global__ void attn_k(const float* __restrict__ Y3, const float* __restrict__ attnW,
                       float* __restrict__ attn)
{
    int b = blockIdx.x, tid = threadIdx.x;
    __shared__ float wae[HH];
    __shared__ float sc[GT];
    __shared__ float red[256];
    wae[tid] = attnW[HH + tid];
    __syncthreads();
    for (int idx = tid; idx < GT; idx += 256){
        int g = idx % GG, t = idx / GG;
        const float* row = Y3 + ((size_t)(t*GT + g*64 + b))*HH;
        float s = 0.f;
        #pragma unroll 4
        for (int h = 0; h < HH; h++) s += row[h]*wae[h];
        sc[idx] = s;
    }
    __syncthreads();
    float mx = -1e30f;
    for (int idx = tid; idx < GT; idx += 256) mx = fmaxf(mx, sc[idx]);
    red[tid] = mx; __syncthreads();
    for (int s = 128; s > 0; s >>= 1){ if (tid < s) red[tid] = fmaxf(red[tid], red[tid+s]); __syncthreads(); }
    mx = red[0]; __syncthreads();
    float sm = 0.f;
    for (int idx = tid; idx < GT; idx += 256){ float e = __expf(sc[idx]-mx); sc[idx] = e; sm += e; }
    red[tid] = sm; __syncthreads();
    for (int s = 128; s > 0; s >>= 1){ if (tid < s) red[tid] += red[tid+s]; __syncthreads(); }
    float inv = 1.f/red[0];
    __syncthreads();
    float a0 = 0.f;
    for (int idx = 0; idx < GT; idx++){
        int g = idx % GG, t = idx / GG;
        a0 += sc[idx]*Y3[((size_t)(t*GT + g*64 + b))*HH + tid];
    }
    attn[b*HH + tid] = a0*inv;
}

__global__ void pack_cin_k(const float* dh0, const float* attn, float* cin)
{
    int b = blockIdx.x, k = threadIdx.x;
    cin[b*512 + k] = (k < HH) ? dh0[b*HH + k] : attn[b*HH + (k - HH)];
}

// ---------------------------------------------------------------------------
// Persistent tensor-core decoder: 64 steps x 4 layers, one launch, 48 blocks.
// Block = 64 rows (target rt, batch 0..63) x 64 permuted gate-cols (16 h).
// ---------------------------------------------------------------------------
__global__ void __launch_bounds__(256, 1) dec_tc_k(
    const float* __restrict__ x, const int* __restrict__ tord,
    const float* __restrict__ cnstP,      // [4][64][1024] permuted
    const float* __restrict__ cinAll,     // [4][64][256]
    const __nv_bfloat16* __restrict__ WHi, const __nv_bfloat16* __restrict__ WLo,
    __nv_bfloat16* __restrict__ D1h, __nv_bfloat16* __restrict__ D1l,
    __nv_bfloat16* __restrict__ D2h, __nv_bfloat16* __restrict__ D2l,
    const float* __restrict__ outW, const float* __restrict__ outB,
    const float* __restrict__ Wemb, const float* __restrict__ bemb,
    float* __restrict__ dout)
{
    uint32_t* sW = sdyn;                   // [2][64][DKP]
    uint32_t* sIn = sdyn + DW_WORDS;       // [2][64][DKP]
    float* sG = reinterpret_cast<float*>(sIn);   // [64][68] aliased
    __shared__ float sRed[64][4][4];
    __shared__ float sOut[64][4];
    __shared__ float sOW[NG];
    __shared__ float sWemb[EE*4];
    __shared__ float sBemb[EE];
    __shared__ float sOutB[4];
    const int tid = threadIdx.x;
    const int lane = tid & 31, wid = tid >> 5;
    const int wm = wid & 1, wn = wid >> 1;        // 2 m x 4 n warps
    const int g = lane >> 2, q = lane & 3;
    const int rt = blockIdx.x / 16, ct = blockIdx.x % 16;
    const unsigned nb = gridDim.x;
    unsigned round = 0;
    const int tordv = *tord;

    for (int i = tid; i < NG; i += 256) sOW[i] = outW[i];
    for (int i = tid; i < EE*4; i += 256) sWemb[i] = Wemb[i];
    if (tid < EE) sBemb[tid] = bemb[tid];
    if (tid < 4) sOutB[tid] = outB[tid];
    __syncthreads();

    const int er = tid >> 2, hq = tid & 3;

    for (int t = 0; t < 64; t++){
        // ---- phase A: build e (bf16 hi/lo) in sIn; emit dout for t-1 ----
        if (t == 0){
            int r = tid >> 2, part = tid & 3;
            const float* xr = x + (((size_t)(r*TT_ + 63))*GG + (tordv + rt))*FF;
            float x0 = xr[0], x1 = xr[1], x2 = xr[2], x3 = xr[3];
            #pragma unroll
            for (int kk = 0; kk < 16; kk++){
                int ee = part*32 + kk*2;
                float v0 = sBemb[ee]   + x0*sWemb[ee*4]     + x1*sWemb[ee*4+1]
                         + x2*sWemb[ee*4+2]   + x3*sWemb[ee*4+3];
                float v1 = sBemb[ee+1] + x0*sWemb[(ee+1)*4] + x1*sWemb[(ee+1)*4+1]
                         + x2*sWemb[(ee+1)*4+2] + x3*sWemb[(ee+1)*4+3];
                v0 = fmaxf(v0, 0.f); v1 = fmaxf(v1, 0.f);
                __nv_bfloat16 h0 = __float2bfloat16(v0), h1 = __float2bfloat16(v1);
                __nv_bfloat162 hv; hv.x = h0; hv.y = h1;
                __nv_bfloat162 lv;
                lv.x = __float2bfloat16(v0 - __bfloat162float(h0));
                lv.y = __float2bfloat16(v1 - __bfloat162float(h1));
                sIn[r*DKP + part*16 + kk] = *reinterpret_cast<uint32_t*>(&hv);
                sIn[64*DKP + r*DKP + part*16 + kk] = *reinterpret_cast<uint32_t*>(&lv);
            }
            __syncthreads();
        } else {
            {
                int r = tid >> 2, seg = tid & 3;
                const __nv_bfloat16* hhp = D2h + ((size_t)(rt*64 + r))*HH + seg*64;
                const __nv_bfloat16* hlp = D2l + ((size_t)(rt*64 + r))*HH + seg*64;
                float po0 = 0.f, po1 = 0.f, po2 = 0.f, po3 = 0.f;
                #pragma unroll 8
                for (int h = 0; h < 64; h += 2){
                    __nv_bfloat162 a = __ldcg(reinterpret_cast<const __nv_bfloat162*>(hhp + h));
                    __nv_bfloat162 bl = __ldcg(reinterpret_cast<const __nv_bfloat162*>(hlp + h));
                    float h0 = __bfloat162float(a.x) + __bfloat162float(bl.x);
                    float h1 = __bfloat162float(a.y) + __bfloat162float(bl.y);
                    int hg = seg*64 + h;
                    po0 += h0*sOW[hg]       + h1*sOW[hg+1];
                    po1 += h0*sOW[HH+hg]    + h1*sOW[HH+hg+1];
                    po2 += h0*sOW[2*HH+hg]  + h1*sOW[2*HH+hg+1];
                    po3 += h0*sOW[3*HH+hg]  + h1*sOW[3*HH+hg+1];
                }
                sRed[r][seg][0] = po0; sRed[r][seg][1] = po1;
                sRed[r][seg][2] = po2; sRed[r][seg][3] = po3;
            }
            __syncthreads();
            {
                int r = tid >> 2, o = tid & 3;
                float v = sRed[r][0][o] + sRed[r][1][o] + sRed[r][2][o] + sRed[r][3][o] + sOutB[o];
                sOut[r][o] = v;
                if (ct == 0)
                    dout[(size_t)r*(TT_*NT*FF) + (size_t)(t-1)*(NT*FF) + rt*FF + o] = v;
            }
            __syncthreads();
            {
                int r = tid >> 2, part = tid & 3;
                float o0 = sOut[r][0], o1 = sOut[r][1], o2 = sOut[r][2], o3 = sOut[r][3];
                #pragma unroll
                for (int kk = 0; kk < 16; kk++){
                    int ee = part*32 + kk*2;
                    float v0 = sBemb[ee]   + o0*sWemb[ee*4]     + o1*sWemb[ee*4+1]
                             + o2*sWemb[ee*4+2]   + o3*sWemb[ee*4+3];
                    float v1 = sBemb[ee+1] + o0*sWemb[(ee+1)*4] + o1*sWemb[(ee+1)*4+1]
                             + o2*sWemb[(ee+1)*4+2] + o3*sWemb[(ee+1)*4+3];
                    v0 = fmaxf(v0, 0.f); v1 = fmaxf(v1, 0.f);
                    __nv_bfloat16 h0 = __float2bfloat16(v0), h1 = __float2bfloat16(v1);
                    __nv_bfloat162 hv; hv.x = h0; hv.y = h1;
                    __nv_bfloat162 lv;
                    lv.x = __float2bfloat16(v0 - __bfloat162float(h0));
                    lv.y = __float2bfloat16(v1 - __bfloat162float(h1));
                    sIn[r*DKP + part*16 + kk] = *reinterpret_cast<uint32_t*>(&hv);
                    sIn[64*DKP + r*DKP + part*16 + kk] = *reinterpret_cast<uint32_t*>(&lv);
                }
            }
            __syncthreads();
        }
        // ---- 4 LSTM layers ----
        #pragma unroll 1
        for (int l = 0; l < 4; l++){
            const int K = l ? HH : EE;
            const size_t loff = l ? ((size_t)NG*EE + (size_t)(l-1)*NG*HH) : 0;
            // stage weights
            {
                int nv = K >> 3;   // uint4 per row
                for (int i = tid; i < 2*64*nv; i += 256){
                    int s = i / (64*nv);
                    int rem = i - s*(64*nv);
                    int row = rem / nv, v4 = rem - row*nv;
                    const __nv_bfloat16* base = (s ? WLo : WHi) + loff + (size_t)(ct*64 + row)*K;
                    *reinterpret_cast<uint4*>(&sW[(s*64 + row)*DKP + v4*4]) =
                        *(reinterpret_cast<const uint4*>(base) + v4);
                }
            }
            // stage inputs (l>0 from global ping-pong)
            if (l > 0){
                const __nv_bfloat16* ih = (l == 2) ? D2h : D1h;
                const __nv_bfloat16* il = (l == 2) ? D2l : D1l;
                for (int i = tid; i < 2*64*32; i += 256){
                    int s = i >> 11;
                    int rem = i & 2047;
                    int row = rem >> 5, v4 = rem & 31;
                    const uint4* src = reinterpret_cast<const uint4*>(
                        (s ? il : ih) + ((size_t)(rt*64 + row))*HH) + v4;
                    uint4 v = __ldcg(src);
                    *reinterpret_cast<uint4*>(&sIn[(s*64 + row)*DKP + v4*4]) = v;
                }
            }
            __syncthreads();
            // mma
            float acc[2][2][4];
            #pragma unroll
            for (int i = 0; i < 2; i++)
                #pragma unroll
                for (int j = 0; j < 2; j++){ acc[i][j][0]=0.f; acc[i][j][1]=0.f; acc[i][j][2]=0.f; acc[i][j][3]=0.f; }
            const int kfmax = K >> 4;
            for (int kf = 0; kf < kfmax; kf++){
                int kp = kf*8 + q;
                uint32_t a[2][2][4];
                #pragma unroll
                for (int fm = 0; fm < 2; fm++){
                    int row = wm*32 + fm*16;
                    #pragma unroll
                    for (int s = 0; s < 2; s++){
                        const uint32_t* base = sIn + s*64*DKP;
                        a[fm][s][0] = base[(row+g)*DKP + kp];
                        a[fm][s][1] = base[(row+g+8)*DKP + kp];
                        a[fm][s][2] = base[(row+g)*DKP + kp+4];
                        a[fm][s][3] = base[(row+g+8)*DKP + kp+4];
                    }
                }
                #pragma unroll
                for (int fn = 0; fn < 2; fn++){
                    int nr = wn*16 + fn*8 + g;
                    uint32_t bh0 = sW[nr*DKP + kp], bh1 = sW[nr*DKP + kp+4];
                    uint32_t bl0 = sW[64*DKP + nr*DKP + kp], bl1 = sW[64*DKP + nr*DKP + kp+4];
                    #pragma unroll
                    for (int fm = 0; fm < 2; fm++){
                        mma_bf16(acc[fm][fn], a[fm][0], bh0, bh1);
                        mma_bf16(acc[fm][fn], a[fm][0], bl0, bl1);
                        mma_bf16(acc[fm][fn], a[fm][1], bh0, bh1);
                    }
                }
            }
            __syncthreads();   // done reading sIn -> reuse as sG
            #pragma unroll
            for (int fm = 0; fm < 2; fm++){
                int r1 = wm*32 + fm*16 + g;
                #pragma unroll
                for (int fn = 0; fn < 2; fn++){
                    int c0 = wn*16 + fn*8 + q*2;
                    *reinterpret_cast<float2*>(&sG[r1*68 + c0]) =
                        make_float2(acc[fm][fn][0], acc[fm][fn][1]);
                    *reinterpret_cast<float2*>(&sG[(r1+8)*68 + c0]) =
                        make_float2(acc[fm][fn][2], acc[fm][fn][3]);
                }
            }
            __syncthreads();
            // LSTM epilogue: thread owns row er, 4 h (hq*4..+3)
            {
                const float* cp = cnstP + ((size_t)(l*64 + er))*NG + ct*64 + hq*16;
                const float* ci = cinAll + ((size_t)(l*64 + er))*HH + ct*16 + hq*4;
                __nv_bfloat16* oh = (l == 0 || l == 2) ? D1h : D2h;
                __nv_bfloat16* ol = (l == 0 || l == 2) ? D1l : D2l;
                size_t ob = ((size_t)(rt*64 + er))*HH + ct*16 + hq*4;
                #pragma unroll
                for (int g2 = 0; g2 < 2; g2++){
                    int cb = hq*16 + g2*8;
                    float4 s0 = *reinterpret_cast<const float4*>(&sG[er*68 + cb]);
                    float4 s1 = *reinterpret_cast<const float4*>(&sG[er*68 + cb + 4]);
                    float4 c0v = *reinterpret_cast<const float4*>(cp + g2*8);
                    float4 c1v = *reinterpret_cast<const float4*>(cp + g2*8 + 4);
                    float gi0 = s0.x + c0v.x, gi1 = s0.y + c0v.y;
                    float gf0 = s0.z + c0v.z, gf1 = s0.w + c0v.w;
                    float gg0 = s1.x + c1v.x, gg1 = s1.y + c1v.y;
                    float go0 = s1.z + c1v.z, go1 = s1.w + c1v.w;
                    float cc0 = ci[g2*2], cc1 = ci[g2*2 + 1];
                    float c20 = fsig(gf0)*cc0 + fsig(gi0)*ftanh(gg0);
                    float c21 = fsig(gf1)*cc1 + fsig(gi1)*ftanh(gg1);
                    float h0 = fsig(go0)*ftanh(c20);
                    float h1 = fsig(go1)*ftanh(c21);
                    __nv_bfloat16 b0 = __float2bfloat16(h0), b1 = __float2bfloat16(h1);
                    __nv_bfloat162 hv; hv.x = b0; hv.y = b1;
                    __nv_bfloat162 lv;
                    lv.x = __float2bfloat16(h0 - __bfloat162float(b0));
                    lv.y = __float2bfloat16(h1 - __bfloat162float(b1));
                    *reinterpret_cast<__nv_bfloat162*>(oh + ob + g2*2) = hv;
                    *reinterpret_cast<__nv_bfloat162*>(ol + ob + g2*2) = lv;
                }
            }
            grid_barrier(nb, round);
        }
    }
    // ---- final out-projection (t = 63) ----
    {
        int r = tid >> 2, seg = tid & 3;
        const __nv_bfloat16* hhp = D2h + ((size_t)(rt*64 + r))*HH + seg*64;
        const __nv_bfloat16* hlp = D2l + ((size_t)(rt*64 + r))*HH + seg*64;
        float po0 = 0.f, po1 = 0.f, po2 = 0.f, po3 = 0.f;
        #pragma unroll 8
        for (int h = 0; h < 64; h += 2){
            __nv_bfloat162 a = __ldcg(reinterpret_cast<const __nv_bfloat162*>(hhp + h));
            __nv_bfloat162 bl = __ldcg(reinterpret_cast<const __nv_bfloat162*>(hlp + h));
            float h0 = __bfloat162float(a.x) + __bfloat162float(bl.x);
            float h1 = __bfloat162float(a.y) + __bfloat162float(bl.y);
            int hg = seg*64 + h;
            po0 += h0*sOW[hg]       + h1*sOW[hg+1];
            po1 += h0*sOW[HH+hg]    + h1*sOW[HH+hg+1];
            po2 += h0*sOW[2*HH+hg]  + h1*sOW[2*HH+hg+1];
            po3 += h0*sOW[3*HH+hg]  + h1*sOW[3*HH+hg+1];
        }
        sRed[r][seg][0] = po0; sRed[r][seg][1] = po1;
        sRed[r][seg][2] = po2; sRed[r][seg][3] = po3;
    }
    __syncthreads();
    if (ct == 0){
        int r = tid >> 2, o = tid & 3;
        float v = sRed[r][0][o] + sRed[r][1][o] + sRed[r][2][o] + sRed[r][3][o] + sOutB[o];
        dout[(size_t)r*(TT_*NT*FF) + 63u*(NT*FF) + rt*FF + o] = v;
    }
}

static float* symaddr(const void* sym)
{
    void* p = nullptr;
    cudaGetSymbolAddress(&p, sym);
    return (float*)p;
}

extern "C" void kernel_launch(void* const* d_in, const int* in_sizes, int n_in,
                              void* d_out, int out_size)
{
    (void)in_sizes; (void)n_in; (void)out_size;
    const float* x       = (const float*)d_in[0];
    const float* encLinW = (const float*)d_in[2];
    const float* encLinB = (const float*)d_in[3];
    const float* encWih0 = (const float*)d_in[4];
    const float* encWihs = (const float*)d_in[5];
    const float* encWhh  = (const float*)d_in[6];
    const float* encBih  = (const float*)d_in[7];
    const float* encBhh  = (const float*)d_in[8];
    const float* decEmbW = (const float*)d_in[9];
    const float* decEmbB = (const float*)d_in[10];
    const float* attnW   = (const float*)d_in[11];
    const float* decWih0 = (const float*)d_in[13];
    const float* decWihs = (const float*)d_in[14];
    const float* decWhh  = (const float*)d_in[15];
    const float* decBih  = (const float*)d_in[16];
    const float* decBhh  = (const float*)d_in[17];
    const float* outW    = (const float*)d_in[18];
    const float* outB    = (const float*)d_in[19];
    const int*   tord    = (const int*)d_in[20];
    float* out = (float*)d_out;

    float* pX = symaddr(g_X);
    float* pY = symaddr(g_Y0);
    float* pC = symaddr(g_Cst);
    __nv_bfloat16* pAhi = (__nv_bfloat16*)symaddr(g_Ahi);
    __nv_bfloat16* pAlo = (__nv_bfloat16*)symaddr(g_Alo);
    __nv_bfloat16* pWihHi = (__nv_bfloat16*)symaddr(g_WihHi);
    __nv_bfloat16* pWihLo = (__nv_bfloat16*)symaddr(g_WihLo);
    __nv_bfloat16* pWhhHi = (__nv_bfloat16*)symaddr(g_WhhHi);
    __nv_bfloat16* pWhhLo = (__nv_bfloat16*)symaddr(g_WhhLo);
    float* pBiasEncP = symaddr(g_biasEncP);
    float* pDecWhhT = symaddr(g_decWhhT);
    float* pPack = symaddr(g_WcPack);
    float* pBiasDec = symaddr(g_biasDec);
    float* pDech = symaddr(g_dech);
    float* pDecc = symaddr(g_decc);
    float* pAttn = symaddr(g_attn);
    float* pCin = symaddr(g_cin);
    float* pConst = symaddr(g_const);
    float* pConstP = symaddr(g_constP);
    __nv_bfloat16* pDWHi = (__nv_bfloat16*)symaddr(g_dWHi);
    __nv_bfloat16* pDWLo = (__nv_bfloat16*)symaddr(g_dWLo);
    __nv_bfloat16* pD1h = (__nv_bfloat16*)symaddr(g_d1h);
    __nv_bfloat16* pD1l = (__nv_bfloat16*)symaddr(g_d1l);
    __nv_bfloat16* pD2h = (__nv_bfloat16*)symaddr(g_d2h);
    __nv_bfloat16* pD2l = (__nv_bfloat16*)symaddr(g_d2l);

    cudaFuncSetAttribute(enc_tc_k, cudaFuncAttributeMaxDynamicSharedMemorySize, SMEM_ENC);
    cudaFuncSetAttribute(dec_tc_k, cudaFuncAttributeMaxDynamicSharedMemorySize, SMEM_DEC);

    dim3 tb(32, 8);
    // encoder weights: permuted bf16 hi/lo splits
    wsplit_perm_k<<<(NG*EE + 255)/256, 256>>>(encWih0, EE, pWihHi, pWihLo);
    for (int l = 1; l < 4; l++)
        wsplit_perm_k<<<(NG*HH + 255)/256, 256>>>(encWihs + (size_t)(l-1)*NG*HH, HH,
                                                  pWihHi + NG*EE + (size_t)(l-1)*NG*HH,
                                                  pWihLo + NG*EE + (size_t)(l-1)*NG*HH);
    for (int l = 0; l < 4; l++)
        wsplit_perm_k<<<(NG*HH + 255)/256, 256>>>(encWhh + (size_t)l*NG*HH, HH,
                                                  pWhhHi + (size_t)l*NG*HH,
                                                  pWhhLo + (size_t)l*NG*HH);
    for (int l = 0; l < 4; l++)
        addv_perm_k<<<4, 256>>>(encBih + l*NG, encBhh + l*NG, pBiasEncP + l*NG);
    // decoder const path (fp32 gemms) + weight splits
    for (int l = 1; l < 4; l++)
        transpose_k<<<dim3(8, 32), tb>>>(decWhh + (size_t)l*NG*HH, HH, NG, HH,
                                         pDecWhhT + (size_t)(l-1)*HH*NG, NG);
    transpose_k<<<dim3(8, 32), tb>>>(decWhh, HH, NG, HH, pPack, NG);
    transpose_k<<<dim3(8, 32), tb>>>(decWih0, 384, NG, HH, pPack + (size_t)HH*NG, NG);
    addv_k<<<16, 256>>>(decBih, decBhh, pBiasDec, 4*NG);
    wsplit_perm2_k<<<(NG*EE + 255)/256, 256>>>(decWih0, 384, 256, EE, pDWHi, pDWLo);
    for (int l = 1; l < 4; l++)
        wsplit_perm2_k<<<(NG*HH + 255)/256, 256>>>(decWihs + (size_t)(l-1)*NG*HH, HH, 0, HH,
                                                   pDWHi + NG*EE + (size_t)(l-1)*NG*HH,
                                                   pDWLo + NG*EE + (size_t)(l-1)*NG*HH);

    // encoder embedding (bf16 hi/lo)
    emb_k<<<MTOT, 128>>>(x, encLinW, encLinB, pAhi, pAlo);

    // encoder: tc input GEMM + persistent tc recurrence per layer
    for (int l = 0; l < 4; l++){
        const __nv_bfloat16* wh = (l == 0) ? pWihHi : (pWihHi + NG*EE + (size_t)(l-1)*NG*HH);
        const __nv_bfloat16* wl = (l == 0) ? pWihLo : (pWihLo + NG*EE + (size_t)(l-1)*NG*HH);
        int Kin = (l == 0) ? EE : HH;
        gemm_tc_k<<<dim3(8, MTOT/128), 256>>>(pAhi, pAlo, wh, wl, pBiasEncP + l*NG, pX, Kin);
        reset_barrier_k<<<1, 1>>>();
        enc_tc_k<<<88, 256, SMEM_ENC>>>(pX, pWhhHi + (size_t)l*NG*HH, pWhhLo + (size_t)l*NG*HH,
                                        pY, pC, pAhi, pAlo);
        snap_k<<<64, 256>>>(pY + (size_t)(TT_-1)*GT*HH, pC, tord,
                            pDech + (size_t)l*BB*HH, pDecc + (size_t)l*BB*HH);
    }

    attn_k<<<BB, 256>>>(pY, attnW, pAttn);
    pack_cin_k<<<BB, 512>>>(pDech, pAttn, pCin);
    gemm_k<<<dim3(8, 1), 256>>>(pCin, pPack, pBiasDec, pConst, BB, NG, 512);
    for (int l = 1; l < 4; l++)
        gemm_k<<<dim3(8, 1), 256>>>(pDech + (size_t)l*BB*HH, pDecWhhT + (size_t)(l-1)*HH*NG,
                                    pBiasDec + l*NG, pConst + (size_t)l*BB*NG, BB, NG, HH);
    perm_const_k<<<(4*BB*NG + 255)/256, 256>>>(pConst, pConstP);

    reset_barrier_k<<<1, 1>>>();
    dec_tc_k<<<DNB, 256, SMEM_DEC>>>(x, tord, pConstP, pDecc, pDWHi, pDWLo,
                                     pD1h, pD1l, pD2h, pD2l,
                                     outW, outB, decEmbW, decEmbB, out);
}

// round 11
// speedup vs baseline: 1.0482x; 1.0482x over previous
#include <cuda_runtime.h>
#include <cuda_bf16.h>
#include <cstdint>

#define BB   64
#define TT_  64
#define GG   11
#define FF   4
#define HH   256
#define EE   128
#define NT   3
#define GT   (GG*BB)     // 704
#define MTOT (TT_*GT)    // 45056
#define NG   1024
#define KSZ  (256*1024)

// encoder tc persistent tile
#define ER 64
#define EC 128
#define BP 132
#define AP 132
#define SB_WORDS (2*128*BP)
#define SA_WORDS (2*64*AP)
#define SMEM_ENC ((SB_WORDS + SA_WORDS)*4)  // 202752 B

__device__ float g_X[MTOT*NG];
__device__ float g_Y0[MTOT*HH];
__device__ float g_Cst[GT*HH];
__device__ __nv_bfloat16 g_Ahi[MTOT*HH];
__device__ __nv_bfloat16 g_Alo[MTOT*HH];
__device__ __nv_bfloat16 g_WihHi[(EE + 3*HH)*NG];
__device__ __nv_bfloat16 g_WihLo[(EE + 3*HH)*NG];
__device__ __nv_bfloat16 g_WhhHi[4*NG*HH];
__device__ __nv_bfloat16 g_WhhLo[4*NG*HH];
__device__ float g_biasEncP[4*NG];
__device__ float g_decWihsT[3*KSZ];
__device__ float g_decWhhT[3*KSZ];
__device__ float g_WcPack[512*NG];
__device__ float g_decWeT[EE*NG];
__device__ float g_biasDec[4*NG];
__device__ float g_dech[4*BB*HH];
__device__ float g_decc[4*BB*HH];
__device__ float g_attn[BB*HH];
__device__ float g_cin[BB*512];
__device__ float g_const[4*BB*NG];
__device__ float g_h1[NT*BB*HH];
__device__ float g_h2[NT*BB*HH];
__device__ unsigned g_bcnt = 0;
__device__ unsigned g_flag = 0;

__device__ __forceinline__ float fsig(float x){ return 1.f/(1.f + __expf(-x)); }
__device__ __forceinline__ float ftanh(float x){ return 1.f - 2.f/(__expf(2.f*x) + 1.f); }

__device__ __host__ __forceinline__ int permn(int n)
{
    int gate = n >> 8, h = n & 255;
    return (h >> 1)*8 + gate*2 + (h & 1);
}

__global__ void reset_barrier_k(){ g_bcnt = 0; g_flag = 0; }

__device__ __forceinline__ void grid_barrier(unsigned nb, unsigned& round)
{
    __syncthreads();
    if (threadIdx.x == 0){
        unsigned target = ++round;
        __threadfence();
        unsigned old = atomicAdd(&g_bcnt, 1u);
        if (old == target*nb - 1u){
            asm volatile("st.release.gpu.global.u32 [%0], %1;"
                         :: "l"(&g_flag), "r"(target) : "memory");
            __threadfence();
        } else {
            unsigned v;
            while (true){
                asm volatile("ld.acquire.gpu.global.u32 %0, [%1];"
                             : "=r"(v) : "l"(&g_flag) : "memory");
                if (v >= target) break;
                __nanosleep(32);
            }
        }
    }
    __syncthreads();
}

__global__ void transpose_k(const float* __restrict__ src, int ldS, int rows, int cols,
                            float* __restrict__ dst, int ldD)
{
    __shared__ float tile[32][33];
    int c0 = blockIdx.x*32, r0 = blockIdx.y*32;
    for (int i = threadIdx.y; i < 32; i += 8){
        int r = r0 + i, c = c0 + threadIdx.x;
        tile[i][threadIdx.x] = (r < rows && c < cols) ? src[(size_t)r*ldS + c] : 0.f;
    }
    __syncthreads();
    for (int i = threadIdx.y; i < 32; i += 8){
        int c = c0 + i, r = r0 + threadIdx.x;
        if (c < cols && r < rows) dst[(size_t)c*ldD + r] = tile[threadIdx.x][i];
    }
}

__global__ void addv_k(const float* a, const float* b, float* o, int n)
{
    int i = blockIdx.x*256 + threadIdx.x;
    if (i < n) o[i] = a[i] + b[i];
}

__global__ void addv_perm_k(const float* __restrict__ a, const float* __restrict__ b,
                            float* __restrict__ o)
{
    int n = blockIdx.x*256 + threadIdx.x;
    if (n < NG) o[permn(n)] = a[n] + b[n];
}

__global__ void wsplit_perm_k(const float* __restrict__ src, int K,
                              __nv_bfloat16* __restrict__ hi, __nv_bfloat16* __restrict__ lo)
{
    int i = blockIdx.x*256 + threadIdx.x;
    if (i < NG*K){
        int n = i / K, k = i - n*K;
        float v = src[i];
        __nv_bfloat16 h = __float2bfloat16(v);
        int d = permn(n)*K + k;
        hi[d] = h;
        lo[d] = __float2bfloat16(v - __bfloat162float(h));
    }
}

__global__ void emb_k(const float* __restrict__ x, const float* __restrict__ W,
                      const float* __restrict__ bias,
                      __nv_bfloat16* __restrict__ hi, __nv_bfloat16* __restrict__ lo)
{
    int m = blockIdx.x;
    int t = m / GT; int rem = m % GT; int g = rem >> 6; int b = rem & 63;
    const float* xr = x + (((size_t)(b*TT_ + t))*GG + g)*FF;
    int e = threadIdx.x;
    float v = bias[e] + xr[0]*W[e*4] + xr[1]*W[e*4+1] + xr[2]*W[e*4+2] + xr[3]*W[e*4+3];
    v = fmaxf(v, 0.f);
    __nv_bfloat16 h = __float2bfloat16(v);
    hi[(size_t)m*EE + e] = h;
    lo[(size_t)m*EE + e] = __float2bfloat16(v - __bfloat162float(h));
}

__device__ __forceinline__ void mma_bf16(float* c, const uint32_t* a, uint32_t b0, uint32_t b1)
{
    asm volatile("mma.sync.aligned.m16n8k16.row.col.f32.bf16.bf16.f32 "
        "{%0,%1,%2,%3}, {%4,%5,%6,%7}, {%8,%9}, {%0,%1,%2,%3};"
        : "+f"(c[0]), "+f"(c[1]), "+f"(c[2]), "+f"(c[3])
        : "r"(a[0]), "r"(a[1]), "r"(a[2]), "r"(a[3]), "r"(b0), "r"(b1));
}

// Tensor-core split-bf16 GEMM: C[M][1024] = A[M][K] @ W[1024][K]^T + bias
__global__ __launch_bounds__(256, 2) void gemm_tc_k(
    const __nv_bfloat16* __restrict__ Ahi, const __nv_bfloat16* __restrict__ Alo,
    const __nv_bfloat16* __restrict__ Whi, const __nv_bfloat16* __restrict__ Wlo,
    const float* __restrict__ bias, float* __restrict__ C, int K)
{
    __shared__ __align__(16) uint32_t sA[2][128][20];
    __shared__ __align__(16) uint32_t sB[2][128][20];
    const int tid = threadIdx.x;
    const int lane = tid & 31, wid = tid >> 5;
    const int wm = wid & 3, wn = wid >> 2;
    const int m0 = blockIdx.y*128, n0 = blockIdx.x*128;
    const int g = lane >> 2, q = lane & 3;
    float acc[2][8][4];
    #pragma unroll
    for (int i = 0; i < 2; i++)
        #pragma unroll
        for (int j = 0; j < 8; j++){ acc[i][j][0]=0.f; acc[i][j][1]=0.f; acc[i][j][2]=0.f; acc[i][j][3]=0.f; }

    for (int k0 = 0; k0 < K; k0 += 32){
        #pragma unroll
        for (int rep = 0; rep < 2; rep++){
            int chunk = tid + rep*256;
            int row = chunk >> 2, off = chunk & 3;
            size_t ga = (size_t)(m0 + row)*K + k0 + off*8;
            size_t gb = (size_t)(n0 + row)*K + k0 + off*8;
            *reinterpret_cast<uint4*>(&sA[0][row][off*4]) = *reinterpret_cast<const uint4*>(Ahi + ga);
            *reinterpret_cast<uint4*>(&sA[1][row][off*4]) = *reinterpret_cast<const uint4*>(Alo + ga);
            *reinterpret_cast<uint4*>(&sB[0][row][off*4]) = *reinterpret_cast<const uint4*>(Whi + gb);
            *reinterpret_cast<uint4*>(&sB[1][row][off*4]) = *reinterpret_cast<const uint4*>(Wlo + gb);
        }
        __syncthreads();
        #pragma unroll
        for (int ks = 0; ks < 2; ks++){
            int kp = q + ks*8;
            uint32_t a[2][2][4];
            #pragma unroll
            for (int fm = 0; fm < 2; fm++){
                int row = wm*32 + fm*16;
                #pragma unroll
                for (int s = 0; s < 2; s++){
                    a[fm][s][0] = sA[s][row+g][kp];
                    a[fm][s][1] = sA[s][row+g+8][kp];
                    a[fm][s][2] = sA[s][row+g][kp+4];
                    a[fm][s][3] = sA[s][row+g+8][kp+4];
                }
            }
            #pragma unroll
            for (int fn = 0; fn < 8; fn++){
                int nr = wn*64 + fn*8 + g;
                uint32_t bh0 = sB[0][nr][kp], bh1 = sB[0][nr][kp+4];
                uint32_t bl0 = sB[1][nr][kp], bl1 = sB[1][nr][kp+4];
                #pragma unroll
                for (int fm = 0; fm < 2; fm++){
                    mma_bf16(acc[fm][fn], a[fm][0], bh0, bh1);
                    mma_bf16(acc[fm][fn], a[fm][0], bl0, bl1);
                    mma_bf16(acc[fm][fn], a[fm][1], bh0, bh1);
                }
            }
        }
        __syncthreads();
    }
    #pragma unroll
    for (int fm = 0; fm < 2; fm++){
        int r = m0 + wm*32 + fm*16 + g;
        #pragma unroll
        for (int fn = 0; fn < 8; fn++){
            int cn = n0 + wn*64 + fn*8 + q*2;
            float b0 = bias[cn], b1 = bias[cn+1];
            float2 v0 = make_float2(acc[fm][fn][0] + b0, acc[fm][fn][1] + b1);
            float2 v1 = make_float2(acc[fm][fn][2] + b0, acc[fm][fn][3] + b1);
            *reinterpret_cast<float2*>(C + (size_t)r*NG + cn) = v0;
            *reinterpret_cast<float2*>(C + (size_t)(r+8)*NG + cn) = v1;
        }
    }
}

// fp32 GEMM (decoder constants)
__global__ void gemm_k(const float* __restrict__ A, const float* __restrict__ B,
                       const float* __restrict__ bias, float* __restrict__ C,
                       int M, int N, int K)
{
    __shared__ float As[8][128];
    __shared__ float Bs[8][128];
    int tid = threadIdx.x;
    int m0 = blockIdx.y*128, n0 = blockIdx.x*128;
    int tx = tid & 15, ty = tid >> 4;
    float acc[8][8];
    #pragma unroll
    for (int i = 0; i < 8; i++)
        #pragma unroll
        for (int j = 0; j < 8; j++) acc[i][j] = 0.f;
    int arow = tid >> 1, acol = (tid & 1)*4;
    int brow = tid >> 5, bcol = (tid & 31)*4;
    for (int k0 = 0; k0 < K; k0 += 8){
        float4 av = make_float4(0.f,0.f,0.f,0.f);
        int gm = m0 + arow;
        if (gm < M) av = *reinterpret_cast<const float4*>(A + (size_t)gm*K + k0 + acol);
        As[acol+0][arow] = av.x; As[acol+1][arow] = av.y;
        As[acol+2][arow] = av.z; As[acol+3][arow] = av.w;
        *reinterpret_cast<float4*>(&Bs[brow][bcol]) =
            *reinterpret_cast<const float4*>(B + (size_t)(k0+brow)*N + n0 + bcol);
        __syncthreads();
        #pragma unroll
        for (int kk = 0; kk < 8; kk++){
            float a[8], b[8];
            *reinterpret_cast<float4*>(a)   = *reinterpret_cast<float4*>(&As[kk][ty*4]);
            *reinterpret_cast<float4*>(a+4) = *reinterpret_cast<float4*>(&As[kk][64+ty*4]);
            *reinterpret_cast<float4*>(b)   = *reinterpret_cast<float4*>(&Bs[kk][tx*4]);
            *reinterpret_cast<float4*>(b+4) = *reinterpret_cast<float4*>(&Bs[kk][64+tx*4]);
            #pragma unroll
            for (int i = 0; i < 8; i++)
                #pragma unroll
                for (int j = 0; j < 8; j++) acc[i][j] += a[i]*b[j];
        }
        __syncthreads();
    }
    #pragma unroll
    for (int i = 0; i < 8; i++){
        int gm = m0 + ((i < 4) ? (ty*4 + i) : (64 + ty*4 + (i-4)));
        if (gm >= M) continue;
        #pragma unroll
        for (int j = 0; j < 8; j++){
            int gn = n0 + ((j < 4) ? (tx*4 + j) : (64 + tx*4 + (j-4)));
            C[(size_t)gm*N + gn] = acc[i][j] + bias[gn];
        }
    }
}

// ---------------------------------------------------------------------------
// Persistent tensor-core encoder layer: 64 steps, one launch, 88 blocks.
// ---------------------------------------------------------------------------
extern __shared__ uint32_t sdyn[];

__global__ void __launch_bounds__(256, 1) enc_tc_k(
    const float* __restrict__ X,
    const __nv_bfloat16* __restrict__ WHi, const __nv_bfloat16* __restrict__ WLo,
    float* __restrict__ Y, float* __restrict__ Cfin,
    __nv_bfloat16* __restrict__ Hhi, __nv_bfloat16* __restrict__ Hlo)
{
    uint32_t* sB = sdyn;
    uint32_t* sA = sdyn + SB_WORDS;
    float* sG = reinterpret_cast<float*>(sA);
    const int tid = threadIdx.x;
    const int lane = tid & 31, wid = tid >> 5;
    const int wm = wid & 1, wn = wid >> 1;
    const int g = lane >> 2, q = lane & 3;
    const int rt = blockIdx.x % 11, ct = blockIdx.x / 11;
    const int m0 = rt*ER, n0 = ct*EC;
    const unsigned nb = gridDim.x;
    unsigned round = 0;

    for (int i = tid; i < 2*128*32; i += 256){
        int s = i >> 12;
        int rem = i & 4095;
        int row = rem >> 5, w4 = rem & 31;
        const uint4* src = reinterpret_cast<const uint4*>(
            (s ? WLo : WHi) + (size_t)(n0 + row)*HH) + w4;
        *reinterpret_cast<uint4*>(&sB[s*128*BP + row*BP + w4*4]) = *src;
    }
    __syncthreads();

    const int erow = tid >> 2;
    const int hb = (tid & 3)*8;
    float c[8];
    #pragma unroll
    for (int e = 0; e < 8; e++) c[e] = 0.f;

    for (int t = 0; t < 64; t++){
        if (t > 0){
            for (int i = tid; i < 2*64*32; i += 256){
                int s = i >> 11;
                int rem = i & 2047;
                int row = rem >> 5, w4 = rem & 31;
                const uint4* src = reinterpret_cast<const uint4*>(
                    (s ? Hlo : Hhi) + ((size_t)(t-1)*GT + m0 + row)*HH) + w4;
                uint4 v = __ldcg(src);
                *reinterpret_cast<uint4*>(&sA[s*64*AP + row*AP + w4*4]) = v;
            }
            __syncthreads();
            float acc[2][4][4];
            #pragma unroll
            for (int i = 0; i < 2; i++)
                #pragma unroll
                for (int j = 0; j < 4; j++){ acc[i][j][0]=0.f; acc[i][j][1]=0.f; acc[i][j][2]=0.f; acc[i][j][3]=0.f; }
            #pragma unroll
            for (int ks = 0; ks < 16; ks++){
                const int kp = ks*8 + q;
                uint32_t a[2][2][4];
                #pragma unroll
                for (int fm = 0; fm < 2; fm++){
                    int row = wm*32 + fm*16;
                    #pragma unroll
                    for (int s = 0; s < 2; s++){
                        const uint32_t* base = sA + s*64*AP;
                        a[fm][s][0] = base[(row+g)*AP + kp];
                        a[fm][s][1] = base[(row+g+8)*AP + kp];
                        a[fm][s][2] = base[(row+g)*AP + kp+4];
                        a[fm][s][3] = base[(row+g+8)*AP + kp+4];
                    }
                }
                #pragma unroll
                for (int fn = 0; fn < 4; fn++){
                    int nr = wn*32 + fn*8 + g;
                    uint32_t bh0 = sB[nr*BP + kp], bh1 = sB[nr*BP + kp+4];
                    uint32_t bl0 = sB[128*BP + nr*BP + kp], bl1 = sB[128*BP + nr*BP + kp+4];
                    #pragma unroll
                    for (int fm = 0; fm < 2; fm++){
                        mma_bf16(acc[fm][fn], a[fm][0], bh0, bh1);
                        mma_bf16(acc[fm][fn], a[fm][0], bl0, bl1);
                        mma_bf16(acc[fm][fn], a[fm][1], bh0, bh1);
                    }
                }
            }
            __syncthreads();
            #pragma unroll
            for (int fm = 0; fm < 2; fm++){
                int r1 = wm*32 + fm*16 + g;
                #pragma unroll
                for (int fn = 0; fn < 4; fn++){
                    int c0 = wn*32 + fn*8 + q*2;
                    *reinterpret_cast<float2*>(&sG[r1*AP + c0]) =
                        make_float2(acc[fm][fn][0], acc[fm][fn][1]);
                    *reinterpret_cast<float2*>(&sG[(r1+8)*AP + c0]) =
                        make_float2(acc[fm][fn][2], acc[fm][fn][3]);
                }
            }
            __syncthreads();
        }
        const float* xp = X + ((size_t)t*GT + m0 + erow)*NG + n0;
        const size_t yb = ((size_t)t*GT + m0 + erow)*HH + ct*32 + hb;
        #pragma unroll
        for (int ep = 0; ep < 4; ep++){
            int h2 = (hb >> 1) + ep;
            int cb = h2*8;
            float4 x0 = *reinterpret_cast<const float4*>(xp + cb);
            float4 x1 = *reinterpret_cast<const float4*>(xp + cb + 4);
            float gi0 = x0.x, gi1 = x0.y, gf0 = x0.z, gf1 = x0.w;
            float gg0 = x1.x, gg1 = x1.y, go0 = x1.z, go1 = x1.w;
            if (t > 0){
                float4 s0 = *reinterpret_cast<const float4*>(&sG[erow*AP + cb]);
                float4 s1 = *reinterpret_cast<const float4*>(&sG[erow*AP + cb + 4]);
                gi0 += s0.x; gi1 += s0.y; gf0 += s0.z; gf1 += s0.w;
                gg0 += s1.x; gg1 += s1.y; go0 += s1.z; go1 += s1.w;
            }
            float c0 = fsig(gf0)*c[ep*2]   + fsig(gi0)*ftanh(gg0);
            float c1 = fsig(gf1)*c[ep*2+1] + fsig(gi1)*ftanh(gg1);
            c[ep*2] = c0; c[ep*2+1] = c1;
            float h0 = fsig(go0)*ftanh(c0);
            float h1 = fsig(go1)*ftanh(c1);
            *reinterpret_cast<float2*>(Y + yb + 2*ep) = make_float2(h0, h1);
            __nv_bfloat16 b0 = __float2bfloat16(h0), b1 = __float2bfloat16(h1);
            __nv_bfloat162 hhv; hhv.x = b0; hhv.y = b1;
            __nv_bfloat162 llv;
            llv.x = __float2bfloat16(h0 - __bfloat162float(b0));
            llv.y = __float2bfloat16(h1 - __bfloat162float(b1));
            *reinterpret_cast<__nv_bfloat162*>(Hhi + yb + 2*ep) = hhv;
            *reinterpret_cast<__nv_bfloat162*>(Hlo + yb + 2*ep) = llv;
        }
        grid_barrier(nb, round);
    }
    const size_t cbse = (size_t)(m0 + erow)*HH + ct*32 + hb;
    #pragma unroll
    for (int e = 0; e < 8; e++) Cfin[cbse + 2*(e>>1) + (e&1)] = c[e];
}

__global__ void snap_k(const float* __restrict__ Yt, const float* __restrict__ C,
                       const int* __restrict__ tord, float* dh, float* dc)
{
    int b = blockIdx.x, h = threadIdx.x;
    int row = (*tord)*64 + b;
    dh[b*HH + h] = Yt[(size_t)row*HH + h];
    dc[b*HH + h] = C[(size_t)row*HH + h];
}

__global__ void attn_k(const float* __restrict__ Y3, const float* __restrict__ attnW,
                       float* __restrict__ attn)
{
    int b = blockIdx.x, tid = threadIdx.x;
    __shared__ float wae[HH];
    __shared__ float sc[GT];
    __shared__ float red[256];
    wae[tid] = attnW[HH + tid];
    __syncthreads();
    for (int idx = tid; idx < GT; idx += 256){
        int g = idx % GG, t = idx / GG;
        const float* row = Y3 + ((size_t)(t*GT + g*64 + b))*HH;
        float s = 0.f;
        #pragma unroll 4
        for (int h = 0; h < HH; h++) s += row[h]*wae[h];
        sc[idx] = s;
    }
    __syncthreads();
    float mx = -1e30f;
    for (int idx = tid; idx < GT; idx += 256) mx = fmaxf(mx, sc[idx]);
    red[tid] = mx; __syncthreads();
    for (int s = 128; s > 0; s >>= 1){ if (tid < s) red[tid] = fmaxf(red[tid], red[tid+s]); __syncthreads(); }
    mx = red[0]; __syncthreads();
    float sm = 0.f;
    for (int idx = tid; idx < GT; idx += 256){ float e = __expf(sc[idx]-mx); sc[idx] = e; sm += e; }
    red[tid] = sm; __syncthreads();
    for (int s = 128; s > 0; s >>= 1){ if (tid < s) red[tid] += red[tid+s]; __syncthreads(); }
    float inv = 1.f/red[0];
    __syncthreads();
    float a0 = 0.f;
    for (int idx = 0; idx < GT; idx++){
        int g = idx % GG, t = idx / GG;
        a0 += sc[idx]*Y3[((size_t)(t*GT + g*64 + b))*HH + tid];
    }
    attn[b*HH + tid] = a0*inv;
}

__global__ void pack_cin_k(const float* dh0, const float* attn, float* cin)
{
    int b = blockIdx.x, k = threadIdx.x;
    cin[b*512 + k] = (k < HH) ? dh0[b*HH + k] : attn[b*HH + (k - HH)];
}

// Persistent decoder: 64 steps x 4 layers, one launch. 96 blocks x 256 thr.
__global__ __launch_bounds__(256, 2) void dec_persist_k(
    const float* __restrict__ x, const int* __restrict__ tord,
    const float* __restrict__ cnst, const float* __restrict__ cinAll,
    const float* __restrict__ WeT, const float* __restrict__ WihsT,
    float* __restrict__ H1, float* __restrict__ H2,
    const float* __restrict__ outW, const float* __restrict__ outB,
    const float* __restrict__ Wemb, const float* __restrict__ bemb,
    float* __restrict__ dout)
{
    __shared__ float sE[16][128];
    __shared__ float sIn[16][33];
    __shared__ float sW[32][4][32];
    __shared__ float sRed[16][16];
    __shared__ float sOut[16][4];
    const int tid = threadIdx.x;
    const int tx = tid & 31, ty = tid >> 5;
    const int jc = blockIdx.x & 7;
    const int m0 = (blockIdx.x >> 3)*16, j0 = jc*32;
    const unsigned nb = gridDim.x;
    unsigned round = 0;
    const int tordv = *tord;
    const int j = j0 + tx;
    for (int t = 0; t < 64; t++){
        if (t == 0){
            for (int idx = tid; idx < 16*128; idx += 256){
                int rr = idx >> 7, e = idx & 127;
                int m = m0 + rr;
                const float* xr = x + (((size_t)((m & 63)*TT_ + 63))*GG + (tordv + (m >> 6)))*FF;
                float v = bemb[e] + xr[0]*Wemb[e*4] + xr[1]*Wemb[e*4+1]
                                  + xr[2]*Wemb[e*4+2] + xr[3]*Wemb[e*4+3];
                sE[rr][e] = fmaxf(v, 0.f);
            }
            __syncthreads();
        } else {
            {
                int r = tid >> 4, sub = tid & 15, o = sub & 3, seg = sub >> 2;
                const float* hrow = H2 + (size_t)(m0 + r)*HH;
                float s = 0.f;
                #pragma unroll 4
                for (int h = seg*64; h < seg*64 + 64; h++)
                    s += __ldcg(hrow + h) * outW[o*HH + h];
                sRed[r][sub] = s;
            }
            __syncthreads();
            if (tid < 64){
                int rr = tid >> 2, oo = tid & 3;
                float v = sRed[rr][oo] + sRed[rr][4+oo] + sRed[rr][8+oo] + sRed[rr][12+oo] + outB[oo];
                sOut[rr][oo] = v;
                if (jc == 0){
                    int m = m0 + rr;
                    dout[(size_t)(m & 63)*(TT_*NT*FF) + (size_t)(t-1)*(NT*FF) + (m >> 6)*FF + oo] = v;
                }
            }
            __syncthreads();
            for (int idx = tid; idx < 16*128; idx += 256){
                int rr = idx >> 7, e = idx & 127;
                float v = bemb[e] + sOut[rr][0]*Wemb[e*4] + sOut[rr][1]*Wemb[e*4+1]
                        + sOut[rr][2]*Wemb[e*4+2] + sOut[rr][3]*Wemb[e*4+3];
                sE[rr][e] = fmaxf(v, 0.f);
            }
            __syncthreads();
        }
        for (int l = 0; l < 4; l++){
            float acc[2][4] = {{0.f,0.f,0.f,0.f},{0.f,0.f,0.f,0.f}};
            const float* Wt = (l == 0) ? WeT : (WihsT + (size_t)(l-1)*KSZ);
            const int K = (l == 0) ? EE : HH;
            const float* In = (l == 2) ? H2 : H1;
            float* Ho = (l == 0 || l == 2) ? H1 : H2;
            for (int k0 = 0; k0 < K; k0 += 32){
                if (l > 0 && tid < 128){
                    int r = tid >> 3, kc = (tid & 7)*4;
                    float4 v = __ldcg(reinterpret_cast<const float4*>(In + (size_t)(m0+r)*HH + k0 + kc));
                    sIn[r][kc] = v.x; sIn[r][kc+1] = v.y; sIn[r][kc+2] = v.z; sIn[r][kc+3] = v.w;
                }
                #pragma unroll
                for (int qq = 0; qq < 16; qq++){
                    int lin = qq*256 + tid;
                    int kr = lin >> 7, col = lin & 127;
                    sW[kr][col >> 5][col & 31] =
                        Wt[(size_t)(k0+kr)*NG + (col >> 5)*HH + j0 + (col & 31)];
                }
                __syncthreads();
                #pragma unroll
                for (int kk = 0; kk < 32; kk++){
                    float w0 = sW[kk][0][tx], w1 = sW[kk][1][tx];
                    float w2 = sW[kk][2][tx], w3 = sW[kk][3][tx];
                    float a0 = (l == 0) ? sE[ty*2][k0+kk]   : sIn[ty*2][kk];
                    float a1 = (l == 0) ? sE[ty*2+1][k0+kk] : sIn[ty*2+1][kk];
                    acc[0][0]+=a0*w0; acc[0][1]+=a0*w1; acc[0][2]+=a0*w2; acc[0][3]+=a0*w3;
                    acc[1][0]+=a1*w0; acc[1][1]+=a1*w1; acc[1][2]+=a1*w2; acc[1][3]+=a1*w3;
                }
                __syncthreads();
            }
            const float* cl = cnst + (size_t)l*BB*NG;
            const float* ci = cinAll + (size_t)l*BB*HH;
            #pragma unroll
            for (int rr = 0; rr < 2; rr++){
                int m = m0 + ty*2 + rr, b = m & 63;
                const float* cp = cl + (size_t)b*NG;
                float gi = acc[rr][0] + cp[j];
                float gf = acc[rr][1] + cp[HH + j];
                float gg = acc[rr][2] + cp[2*HH + j];
                float go = acc[rr][3] + cp[3*HH + j];
                float c2 = fsig(gf)*ci[b*HH + j] + fsig(gi)*ftanh(gg);
                Ho[(size_t)m*HH + j] = fsig(go)*ftanh(c2);
            }
            grid_barrier(nb, round);
        }
    }
    {
        int r = tid >> 4, sub = tid & 15, o = sub & 3, seg = sub >> 2;
        const float* hrow = H2 + (size_t)(m0 + r)*HH;
        float s = 0.f;
        #pragma unroll 4
        for (int h = seg*64; h < seg*64 + 64; h++)
            s += __ldcg(hrow + h) * outW[o*HH + h];
        sRed[r][sub] = s;
    }
    __syncthreads();
    if (tid < 64 && jc == 0){
        int rr = tid >> 2, oo = tid & 3;
        float v = sRed[rr][oo] + sRed[rr][4+oo] + sRed[rr][8+oo] + sRed[rr][12+oo] + outB[oo];
        int m = m0 + rr;
        dout[(size_t)(m & 63)*(TT_*NT*FF) + 63u*(NT*FF) + (m >> 6)*FF + oo] = v;
    }
}

static float* symaddr(const void* sym)
{
    void* p = nullptr;
    cudaGetSymbolAddress(&p, sym);
    return (float*)p;
}

extern "C" void kernel_launch(void* const* d_in, const int* in_sizes, int n_in,
                              void* d_out, int out_size)
{
    (void)in_sizes; (void)n_in; (void)out_size;
    const float* x       = (const float*)d_in[0];
    const float* encLinW = (const float*)d_in[2];
    const float* encLinB = (const float*)d_in[3];
    const float* encWih0 = (const float*)d_in[4];
    const float* encWihs = (const float*)d_in[5];
    const float* encWhh  = (const float*)d_in[6];
    const float* encBih  = (const float*)d_in[7];
    const float* encBhh  = (const float*)d_in[8];
    const float* decEmbW = (const float*)d_in[9];
    const float* decEmbB = (const float*)d_in[10];
    const float* attnW   = (const float*)d_in[11];
    const float* decWih0 = (const float*)d_in[13];
    const float* decWihs = (const float*)d_in[14];
    const float* decWhh  = (const float*)d_in[15];
    const float* decBih  = (const float*)d_in[16];
    const float* decBhh  = (const float*)d_in[17];
    const float* outW    = (const float*)d_in[18];
    const float* outB    = (const float*)d_in[19];
    const int*   tord    = (const int*)d_in[20];
    float* out = (float*)d_out;

    float* pX = symaddr(g_X);
    float* pY = symaddr(g_Y0);
    float* pC = symaddr(g_Cst);
    __nv_bfloat16* pAhi = (__nv_bfloat16*)symaddr(g_Ahi);
    __nv_bfloat16* pAlo = (__nv_bfloat16*)symaddr(g_Alo);
    __nv_bfloat16* pWihHi = (__nv_bfloat16*)symaddr(g_WihHi);
    __nv_bfloat16* pWihLo = (__nv_bfloat16*)symaddr(g_WihLo);
    __nv_bfloat16* pWhhHi = (__nv_bfloat16*)symaddr(g_WhhHi);
    __nv_bfloat16* pWhhLo = (__nv_bfloat16*)symaddr(g_WhhLo);
    float* pBiasEncP = symaddr(g_biasEncP);
    float* pDecWihsT = symaddr(g_decWihsT);
    float* pDecWhhT = symaddr(g_decWhhT);
    float* pPack = symaddr(g_WcPack);
    float* pWeT = symaddr(g_decWeT);
    float* pBiasDec = symaddr(g_biasDec);
    float* pDech = symaddr(g_dech);
    float* pDecc = symaddr(g_decc);
    float* pAttn = symaddr(g_attn);
    float* pCin = symaddr(g_cin);
    float* pConst = symaddr(g_const);
    float* pH1 = symaddr(g_h1);
    float* pH2 = symaddr(g_h2);

    cudaFuncSetAttribute(enc_tc_k, cudaFuncAttributeMaxDynamicSharedMemorySize, SMEM_ENC);

    dim3 tb(32, 8);
    wsplit_perm_k<<<(NG*EE + 255)/256, 256>>>(encWih0, EE, pWihHi, pWihLo);
    for (int l = 1; l < 4; l++)
        wsplit_perm_k<<<(NG*HH + 255)/256, 256>>>(encWihs + (size_t)(l-1)*NG*HH, HH,
                                                  pWihHi + NG*EE + (size_t)(l-1)*NG*HH,
                                                  pWihLo + NG*EE + (size_t)(l-1)*NG*HH);
    for (int l = 0; l < 4; l++)
        wsplit_perm_k<<<(NG*HH + 255)/256, 256>>>(encWhh + (size_t)l*NG*HH, HH,
                                                  pWhhHi + (size_t)l*NG*HH,
                                                  pWhhLo + (size_t)l*NG*HH);
    for (int l = 0; l < 4; l++)
        addv_perm_k<<<4, 256>>>(encBih + l*NG, encBhh + l*NG, pBiasEncP + l*NG);
    for (int l = 0; l < 3; l++)
        transpose_k<<<dim3(8, 32), tb>>>(decWihs + (size_t)l*NG*HH, HH, NG, HH, pDecWihsT + (size_t)l*KSZ, NG);
    for (int l = 1; l < 4; l++)
        transpose_k<<<dim3(8, 32), tb>>>(decWhh + (size_t)l*NG*HH, HH, NG, HH, pDecWhhT + (size_t)(l-1)*KSZ, NG);
    transpose_k<<<dim3(8, 32), tb>>>(decWhh, HH, NG, HH, pPack, NG);
    transpose_k<<<dim3(8, 32), tb>>>(decWih0, 384, NG, HH, pPack + (size_t)HH*NG, NG);
    transpose_k<<<dim3(4, 32), tb>>>(decWih0 + HH, 384, NG, EE, pWeT, NG);
    addv_k<<<16, 256>>>(decBih, decBhh, pBiasDec, 4*NG);

    emb_k<<<MTOT, 128>>>(x, encLinW, encLinB, pAhi, pAlo);

    for (int l = 0; l < 4; l++){
        const __nv_bfloat16* wh = (l == 0) ? pWihHi : (pWihHi + NG*EE + (size_t)(l-1)*NG*HH);
        const __nv_bfloat16* wl = (l == 0) ? pWihLo : (pWihLo + NG*EE + (size_t)(l-1)*NG*HH);
        int Kin = (l == 0) ? EE : HH;
        gemm_tc_k<<<dim3(8, MTOT/128), 256>>>(pAhi, pAlo, wh, wl, pBiasEncP + l*NG, pX, Kin);
        reset_barrier_k<<<1, 1>>>();
        enc_tc_k<<<88, 256, SMEM_ENC>>>(pX, pWhhHi + (size_t)l*NG*HH, pWhhLo + (size_t)l*NG*HH,
                                        pY, pC, pAhi, pAlo);
        snap_k<<<64, 256>>>(pY + (size_t)(TT_-1)*GT*HH, pC, tord,
                            pDech + (size_t)l*BB*HH, pDecc + (size_t)l*BB*HH);
    }

    attn_k<<<BB, 256>>>(pY, attnW, pAttn);
    pack_cin_k<<<BB, 512>>>(pDech, pAttn, pCin);
    gemm_k<<<dim3(8, 1), 256>>>(pCin, pPack, pBiasDec, pConst, BB, NG, 512);
    for (int l = 1; l < 4; l++)
        gemm_k<<<dim3(8, 1), 256>>>(pDech + (size_t)l*BB*HH, pDecWhhT + (size_t)(l-1)*KSZ,
                                    pBiasDec + l*NG, pConst + (size_t)l*BB*NG, BB, NG, HH);

    reset_barrier_k<<<1, 1>>>();
    dec_persist_k<<<96, 256>>>(x, tord, pConst, pDecc, pWeT, pDecWihsT,
                               pH1, pH2, outW, outB, decEmbW, decEmbB, out);
}

// round 12
// speedup vs baseline: 1.1474x; 1.0947x over previous
#include <cuda_runtime.h>
#include <cuda_bf16.h>
#include <cstdint>

#define BB   64
#define TT_  64
#define GG   11
#define FF   4
#define HH   256
#define EE   128
#define NT   3
#define GT   (GG*BB)     // 704
#define MTOT (TT_*GT)    // 45056
#define NG   1024
#define KSZ  (256*1024)

// encoder tc persistent tile
#define ER 64
#define EC 128
#define BP 132
#define AP 132
#define SB_WORDS (2*128*BP)
#define SA_WORDS (2*64*AP)
#define SMEM_ENC ((SB_WORDS + SA_WORDS)*4)  // 202752 B

__device__ float g_X[MTOT*NG];
__device__ float g_Y0[MTOT*HH];
__device__ float g_Cst[GT*HH];
__device__ __nv_bfloat16 g_Ahi[MTOT*HH];
__device__ __nv_bfloat16 g_Alo[MTOT*HH];
__device__ __nv_bfloat16 g_WihHi[(EE + 3*HH)*NG];
__device__ __nv_bfloat16 g_WihLo[(EE + 3*HH)*NG];
__device__ __nv_bfloat16 g_WhhHi[4*NG*HH];
__device__ __nv_bfloat16 g_WhhLo[4*NG*HH];
__device__ float g_biasEncP[4*NG];
__device__ float g_decWihsT[3*KSZ];
__device__ float g_decWhhT[3*KSZ];
__device__ float g_WcPack[512*NG];
__device__ float g_decWeT[EE*NG];
__device__ float g_biasDec[4*NG];
__device__ float g_dech[4*BB*HH];
__device__ float g_decc[4*BB*HH];
__device__ float g_attn[BB*HH];
__device__ float g_cin[BB*512];
__device__ float g_const[4*BB*NG];
__device__ float g_h1[NT*BB*HH];
__device__ float g_h2[NT*BB*HH];
__device__ unsigned g_bcnt = 0;
__device__ unsigned g_flag = 0;

// HW tanh (sm_75+): 1 MUFU op, no division.
__device__ __forceinline__ float ftanh(float x)
{
    float t;
    asm("tanh.approx.f32 %0, %1;" : "=f"(t) : "f"(x));
    return t;
}
// sigmoid(x) = 0.5*tanh(0.5x) + 0.5 : 1 MUFU + 2 FMA
__device__ __forceinline__ float fsig(float x)
{
    return fmaf(ftanh(0.5f*x), 0.5f, 0.5f);
}

__device__ __host__ __forceinline__ int permn(int n)
{
    int gate = n >> 8, h = n & 255;
    return (h >> 1)*8 + gate*2 + (h & 1);
}

__global__ void reset_barrier_k(){ g_bcnt = 0; g_flag = 0; }

__device__ __forceinline__ void grid_barrier(unsigned nb, unsigned& round)
{
    __syncthreads();
    if (threadIdx.x == 0){
        unsigned target = ++round;
        __threadfence();
        unsigned old = atomicAdd(&g_bcnt, 1u);
        if (old == target*nb - 1u){
            asm volatile("st.release.gpu.global.u32 [%0], %1;"
                         :: "l"(&g_flag), "r"(target) : "memory");
            __threadfence();
        } else {
            unsigned v;
            while (true){
                asm volatile("ld.acquire.gpu.global.u32 %0, [%1];"
                             : "=r"(v) : "l"(&g_flag) : "memory");
                if (v >= target) break;
                __nanosleep(32);
            }
        }
    }
    __syncthreads();
}

__global__ void transpose_k(const float* __restrict__ src, int ldS, int rows, int cols,
                            float* __restrict__ dst, int ldD)
{
    __shared__ float tile[32][33];
    int c0 = blockIdx.x*32, r0 = blockIdx.y*32;
    for (int i = threadIdx.y; i < 32; i += 8){
        int r = r0 + i, c = c0 + threadIdx.x;
        tile[i][threadIdx.x] = (r < rows && c < cols) ? src[(size_t)r*ldS + c] : 0.f;
    }
    __syncthreads();
    for (int i = threadIdx.y; i < 32; i += 8){
        int c = c0 + i, r = r0 + threadIdx.x;
        if (c < cols && r < rows) dst[(size_t)c*ldD + r] = tile[threadIdx.x][i];
    }
}

__global__ void addv_k(const float* a, const float* b, float* o, int n)
{
    int i = blockIdx.x*256 + threadIdx.x;
    if (i < n) o[i] = a[i] + b[i];
}

__global__ void addv_perm_k(const float* __restrict__ a, const float* __restrict__ b,
                            float* __restrict__ o)
{
    int n = blockIdx.x*256 + threadIdx.x;
    if (n < NG) o[permn(n)] = a[n] + b[n];
}

__global__ void wsplit_perm_k(const float* __restrict__ src, int K,
                              __nv_bfloat16* __restrict__ hi, __nv_bfloat16* __restrict__ lo)
{
    int i = blockIdx.x*256 + threadIdx.x;
    if (i < NG*K){
        int n = i / K, k = i - n*K;
        float v = src[i];
        __nv_bfloat16 h = __float2bfloat16(v);
        int d = permn(n)*K + k;
        hi[d] = h;
        lo[d] = __float2bfloat16(v - __bfloat162float(h));
    }
}

__global__ void emb_k(const float* __restrict__ x, const float* __restrict__ W,
                      const float* __restrict__ bias,
                      __nv_bfloat16* __restrict__ hi, __nv_bfloat16* __restrict__ lo)
{
    int m = blockIdx.x;
    int t = m / GT; int rem = m % GT; int g = rem >> 6; int b = rem & 63;
    const float* xr = x + (((size_t)(b*TT_ + t))*GG + g)*FF;
    int e = threadIdx.x;
    float v = bias[e] + xr[0]*W[e*4] + xr[1]*W[e*4+1] + xr[2]*W[e*4+2] + xr[3]*W[e*4+3];
    v = fmaxf(v, 0.f);
    __nv_bfloat16 h = __float2bfloat16(v);
    hi[(size_t)m*EE + e] = h;
    lo[(size_t)m*EE + e] = __float2bfloat16(v - __bfloat162float(h));
}

__device__ __forceinline__ void mma_bf16(float* c, const uint32_t* a, uint32_t b0, uint32_t b1)
{
    asm volatile("mma.sync.aligned.m16n8k16.row.col.f32.bf16.bf16.f32 "
        "{%0,%1,%2,%3}, {%4,%5,%6,%7}, {%8,%9}, {%0,%1,%2,%3};"
        : "+f"(c[0]), "+f"(c[1]), "+f"(c[2]), "+f"(c[3])
        : "r"(a[0]), "r"(a[1]), "r"(a[2]), "r"(a[3]), "r"(b0), "r"(b1));
}

// Tensor-core split-bf16 GEMM: C[M][1024] = A[M][K] @ W[1024][K]^T + bias
__global__ __launch_bounds__(256, 2) void gemm_tc_k(
    const __nv_bfloat16* __restrict__ Ahi, const __nv_bfloat16* __restrict__ Alo,
    const __nv_bfloat16* __restrict__ Whi, const __nv_bfloat16* __restrict__ Wlo,
    const float* __restrict__ bias, float* __restrict__ C, int K)
{
    __shared__ __align__(16) uint32_t sA[2][128][20];
    __shared__ __align__(16) uint32_t sB[2][128][20];
    const int tid = threadIdx.x;
    const int lane = tid & 31, wid = tid >> 5;
    const int wm = wid & 3, wn = wid >> 2;
    const int m0 = blockIdx.y*128, n0 = blockIdx.x*128;
    const int g = lane >> 2, q = lane & 3;
    float acc[2][8][4];
    #pragma unroll
    for (int i = 0; i < 2; i++)
        #pragma unroll
        for (int j = 0; j < 8; j++){ acc[i][j][0]=0.f; acc[i][j][1]=0.f; acc[i][j][2]=0.f; acc[i][j][3]=0.f; }

    for (int k0 = 0; k0 < K; k0 += 32){
        #pragma unroll
        for (int rep = 0; rep < 2; rep++){
            int chunk = tid + rep*256;
            int row = chunk >> 2, off = chunk & 3;
            size_t ga = (size_t)(m0 + row)*K + k0 + off*8;
            size_t gb = (size_t)(n0 + row)*K + k0 + off*8;
            *reinterpret_cast<uint4*>(&sA[0][row][off*4]) = *reinterpret_cast<const uint4*>(Ahi + ga);
            *reinterpret_cast<uint4*>(&sA[1][row][off*4]) = *reinterpret_cast<const uint4*>(Alo + ga);
            *reinterpret_cast<uint4*>(&sB[0][row][off*4]) = *reinterpret_cast<const uint4*>(Whi + gb);
            *reinterpret_cast<uint4*>(&sB[1][row][off*4]) = *reinterpret_cast<const uint4*>(Wlo + gb);
        }
        __syncthreads();
        #pragma unroll
        for (int ks = 0; ks < 2; ks++){
            int kp = q + ks*8;
            uint32_t a[2][2][4];
            #pragma unroll
            for (int fm = 0; fm < 2; fm++){
                int row = wm*32 + fm*16;
                #pragma unroll
                for (int s = 0; s < 2; s++){
                    a[fm][s][0] = sA[s][row+g][kp];
                    a[fm][s][1] = sA[s][row+g+8][kp];
                    a[fm][s][2] = sA[s][row+g][kp+4];
                    a[fm][s][3] = sA[s][row+g+8][kp+4];
                }
            }
            #pragma unroll
            for (int fn = 0; fn < 8; fn++){
                int nr = wn*64 + fn*8 + g;
                uint32_t bh0 = sB[0][nr][kp], bh1 = sB[0][nr][kp+4];
                uint32_t bl0 = sB[1][nr][kp], bl1 = sB[1][nr][kp+4];
                #pragma unroll
                for (int fm = 0; fm < 2; fm++){
                    mma_bf16(acc[fm][fn], a[fm][0], bh0, bh1);
                    mma_bf16(acc[fm][fn], a[fm][0], bl0, bl1);
                    mma_bf16(acc[fm][fn], a[fm][1], bh0, bh1);
                }
            }
        }
        __syncthreads();
    }
    #pragma unroll
    for (int fm = 0; fm < 2; fm++){
        int r = m0 + wm*32 + fm*16 + g;
        #pragma unroll
        for (int fn = 0; fn < 8; fn++){
            int cn = n0 + wn*64 + fn*8 + q*2;
            float b0 = bias[cn], b1 = bias[cn+1];
            float2 v0 = make_float2(acc[fm][fn][0] + b0, acc[fm][fn][1] + b1);
            float2 v1 = make_float2(acc[fm][fn][2] + b0, acc[fm][fn][3] + b1);
            *reinterpret_cast<float2*>(C + (size_t)r*NG + cn) = v0;
            *reinterpret_cast<float2*>(C + (size_t)(r+8)*NG + cn) = v1;
        }
    }
}

// fp32 GEMM (decoder constants)
__global__ void gemm_k(const float* __restrict__ A, const float* __restrict__ B,
                       const float* __restrict__ bias, float* __restrict__ C,
                       int M, int N, int K)
{
    __shared__ float As[8][128];
    __shared__ float Bs[8][128];
    int tid = threadIdx.x;
    int m0 = blockIdx.y*128, n0 = blockIdx.x*128;
    int tx = tid & 15, ty = tid >> 4;
    float acc[8][8];
    #pragma unroll
    for (int i = 0; i < 8; i++)
        #pragma unroll
        for (int j = 0; j < 8; j++) acc[i][j] = 0.f;
    int arow = tid >> 1, acol = (tid & 1)*4;
    int brow = tid >> 5, bcol = (tid & 31)*4;
    for (int k0 = 0; k0 < K; k0 += 8){
        float4 av = make_float4(0.f,0.f,0.f,0.f);
        int gm = m0 + arow;
        if (gm < M) av = *reinterpret_cast<const float4*>(A + (size_t)gm*K + k0 + acol);
        As[acol+0][arow] = av.x; As[acol+1][arow] = av.y;
        As[acol+2][arow] = av.z; As[acol+3][arow] = av.w;
        *reinterpret_cast<float4*>(&Bs[brow][bcol]) =
            *reinterpret_cast<const float4*>(B + (size_t)(k0+brow)*N + n0 + bcol);
        __syncthreads();
        #pragma unroll
        for (int kk = 0; kk < 8; kk++){
            float a[8], b[8];
            *reinterpret_cast<float4*>(a)   = *reinterpret_cast<float4*>(&As[kk][ty*4]);
            *reinterpret_cast<float4*>(a+4) = *reinterpret_cast<float4*>(&As[kk][64+ty*4]);
            *reinterpret_cast<float4*>(b)   = *reinterpret_cast<float4*>(&Bs[kk][tx*4]);
            *reinterpret_cast<float4*>(b+4) = *reinterpret_cast<float4*>(&Bs[kk][64+tx*4]);
            #pragma unroll
            for (int i = 0; i < 8; i++)
                #pragma unroll
                for (int j = 0; j < 8; j++) acc[i][j] += a[i]*b[j];
        }
        __syncthreads();
    }
    #pragma unroll
    for (int i = 0; i < 8; i++){
        int gm = m0 + ((i < 4) ? (ty*4 + i) : (64 + ty*4 + (i-4)));
        if (gm >= M) continue;
        #pragma unroll
        for (int j = 0; j < 8; j++){
            int gn = n0 + ((j < 4) ? (tx*4 + j) : (64 + tx*4 + (j-4)));
            C[(size_t)gm*N + gn] = acc[i][j] + bias[gn];
        }
    }
}

// ---------------------------------------------------------------------------
// Persistent tensor-core encoder layer: 64 steps, one launch, 88 blocks.
// ---------------------------------------------------------------------------
extern __shared__ uint32_t sdyn[];

__global__ void __launch_bounds__(256, 1) enc_tc_k(
    const float* __restrict__ X,
    const __nv_bfloat16* __restrict__ WHi, const __nv_bfloat16* __restrict__ WLo,
    float* __restrict__ Y, float* __restrict__ Cfin,
    __nv_bfloat16* __restrict__ Hhi, __nv_bfloat16* __restrict__ Hlo)
{
    uint32_t* sB = sdyn;
    uint32_t* sA = sdyn + SB_WORDS;
    float* sG = reinterpret_cast<float*>(sA);
    const int tid = threadIdx.x;
    const int lane = tid & 31, wid = tid >> 5;
    const int wm = wid & 1, wn = wid >> 1;
    const int g = lane >> 2, q = lane & 3;
    const int rt = blockIdx.x % 11, ct = blockIdx.x / 11;
    const int m0 = rt*ER, n0 = ct*EC;
    const unsigned nb = gridDim.x;
    unsigned round = 0;

    for (int i = tid; i < 2*128*32; i += 256){
        int s = i >> 12;
        int rem = i & 4095;
        int row = rem >> 5, w4 = rem & 31;
        const uint4* src = reinterpret_cast<const uint4*>(
            (s ? WLo : WHi) + (size_t)(n0 + row)*HH) + w4;
        *reinterpret_cast<uint4*>(&sB[s*128*BP + row*BP + w4*4]) = *src;
    }
    __syncthreads();

    const int erow = tid >> 2;
    const int hb = (tid & 3)*8;
    float c[8];
    #pragma unroll
    for (int e = 0; e < 8; e++) c[e] = 0.f;

    for (int t = 0; t < 64; t++){
        if (t > 0){
            for (int i = tid; i < 2*64*32; i += 256){
                int s = i >> 11;
                int rem = i & 2047;
                int row = rem >> 5, w4 = rem & 31;
                const uint4* src = reinterpret_cast<const uint4*>(
                    (s ? Hlo : Hhi) + ((size_t)(t-1)*GT + m0 + row)*HH) + w4;
                uint4 v = __ldcg(src);
                *reinterpret_cast<uint4*>(&sA[s*64*AP + row*AP + w4*4]) = v;
            }
            __syncthreads();
            float acc[2][4][4];
            #pragma unroll
            for (int i = 0; i < 2; i++)
                #pragma unroll
                for (int j = 0; j < 4; j++){ acc[i][j][0]=0.f; acc[i][j][1]=0.f; acc[i][j][2]=0.f; acc[i][j][3]=0.f; }
            #pragma unroll
            for (int ks = 0; ks < 16; ks++){
                const int kp = ks*8 + q;
                uint32_t a[2][2][4];
                #pragma unroll
                for (int fm = 0; fm < 2; fm++){
                    int row = wm*32 + fm*16;
                    #pragma unroll
                    for (int s = 0; s < 2; s++){
                        const uint32_t* base = sA + s*64*AP;
                        a[fm][s][0] = base[(row+g)*AP + kp];
                        a[fm][s][1] = base[(row+g+8)*AP + kp];
                        a[fm][s][2] = base[(row+g)*AP + kp+4];
                        a[fm][s][3] = base[(row+g+8)*AP + kp+4];
                    }
                }
                #pragma unroll
                for (int fn = 0; fn < 4; fn++){
                    int nr = wn*32 + fn*8 + g;
                    uint32_t bh0 = sB[nr*BP + kp], bh1 = sB[nr*BP + kp+4];
                    uint32_t bl0 = sB[128*BP + nr*BP + kp], bl1 = sB[128*BP + nr*BP + kp+4];
                    #pragma unroll
                    for (int fm = 0; fm < 2; fm++){
                        mma_bf16(acc[fm][fn], a[fm][0], bh0, bh1);
                        mma_bf16(acc[fm][fn], a[fm][0], bl0, bl1);
                        mma_bf16(acc[fm][fn], a[fm][1], bh0, bh1);
                    }
                }
            }
            __syncthreads();
            #pragma unroll
            for (int fm = 0; fm < 2; fm++){
                int r1 = wm*32 + fm*16 + g;
                #pragma unroll
                for (int fn = 0; fn < 4; fn++){
                    int c0 = wn*32 + fn*8 + q*2;
                    *reinterpret_cast<float2*>(&sG[r1*AP + c0]) =
                        make_float2(acc[fm][fn][0], acc[fm][fn][1]);
                    *reinterpret_cast<float2*>(&sG[(r1+8)*AP + c0]) =
                        make_float2(acc[fm][fn][2], acc[fm][fn][3]);
                }
            }
            __syncthreads();
        }
        const float* xp = X + ((size_t)t*GT + m0 + erow)*NG + n0;
        const size_t yb = ((size_t)t*GT + m0 + erow)*HH + ct*32 + hb;
        #pragma unroll
        for (int ep = 0; ep < 4; ep++){
            int h2 = (hb >> 1) + ep;
            int cb = h2*8;
            float4 x0 = *reinterpret_cast<const float4*>(xp + cb);
            float4 x1 = *reinterpret_cast<const float4*>(xp + cb + 4);
            float gi0 = x0.x, gi1 = x0.y, gf0 = x0.z, gf1 = x0.w;
            float gg0 = x1.x, gg1 = x1.y, go0 = x1.z, go1 = x1.w;
            if (t > 0){
                float4 s0 = *reinterpret_cast<const float4*>(&sG[erow*AP + cb]);
                float4 s1 = *reinterpret_cast<const float4*>(&sG[erow*AP + cb + 4]);
                gi0 += s0.x; gi1 += s0.y; gf0 += s0.z; gf1 += s0.w;
                gg0 += s1.x; gg1 += s1.y; go0 += s1.z; go1 += s1.w;
            }
            float c0 = fsig(gf0)*c[ep*2]   + fsig(gi0)*ftanh(gg0);
            float c1 = fsig(gf1)*c[ep*2+1] + fsig(gi1)*ftanh(gg1);
            c[ep*2] = c0; c[ep*2+1] = c1;
            float h0 = fsig(go0)*ftanh(c0);
            float h1 = fsig(go1)*ftanh(c1);
            *reinterpret_cast<float2*>(Y + yb + 2*ep) = make_float2(h0, h1);
            __nv_bfloat16 b0 = __float2bfloat16(h0), b1 = __float2bfloat16(h1);
            __nv_bfloat162 hhv; hhv.x = b0; hhv.y = b1;
            __nv_bfloat162 llv;
            llv.x = __float2bfloat16(h0 - __bfloat162float(b0));
            llv.y = __float2bfloat16(h1 - __bfloat162float(b1));
            *reinterpret_cast<__nv_bfloat162*>(Hhi + yb + 2*ep) = hhv;
            *reinterpret_cast<__nv_bfloat162*>(Hlo + yb + 2*ep) = llv;
        }
        grid_barrier(nb, round);
    }
    const size_t cbse = (size_t)(m0 + erow)*HH + ct*32 + hb;
    #pragma unroll
    for (int e = 0; e < 8; e++) Cfin[cbse + 2*(e>>1) + (e&1)] = c[e];
}

__global__ void snap_k(const float* __restrict__ Yt, const float* __restrict__ C,
                       const int* __restrict__ tord, float* dh, float* dc)
{
    int b = blockIdx.x, h = threadIdx.x;
    int row = (*tord)*64 + b;
    dh[b*HH + h] = Yt[(size_t)row*HH + h];
    dc[b*HH + h] = C[(size_t)row*HH + h];
}

__global__ void attn_k(const float* __restrict__ Y3, const float* __restrict__ attnW,
                       float* __restrict__ attn)
{
    int b = blockIdx.x, tid = threadIdx.x;
    __shared__ float wae[HH];
    __shared__ float sc[GT];
    __shared__ float red[256];
    wae[tid] = attnW[HH + tid];
    __syncthreads();
    for (int idx = tid; idx < GT; idx += 256){
        int g = idx % GG, t = idx / GG;
        const float* row = Y3 + ((size_t)(t*GT + g*64 + b))*HH;
        float s = 0.f;
        #pragma unroll 4
        for (int h = 0; h < HH; h++) s += row[h]*wae[h];
        sc[idx] = s;
    }
    __syncthreads();
    float mx = -1e30f;
    for (int idx = tid; idx < GT; idx += 256) mx = fmaxf(mx, sc[idx]);
    red[tid] = mx; __syncthreads();
    for (int s = 128; s > 0; s >>= 1){ if (tid < s) red[tid] = fmaxf(red[tid], red[tid+s]); __syncthreads(); }
    mx = red[0]; __syncthreads();
    float sm = 0.f;
    for (int idx = tid; idx < GT; idx += 256){ float e = __expf(sc[idx]-mx); sc[idx] = e; sm += e; }
    red[tid] = sm; __syncthreads();
    for (int s = 128; s > 0; s >>= 1){ if (tid < s) red[tid] += red[tid+s]; __syncthreads(); }
    float inv = __fdividef(1.f, red[0]);
    __syncthreads();
    float a0 = 0.f;
    for (int idx = 0; idx < GT; idx++){
        int g = idx % GG, t = idx / GG;
        a0 += sc[idx]*Y3[((size_t)(t*GT + g*64 + b))*HH + tid];
    }
    attn[b*HH + tid] = a0*inv;
}

__global__ void pack_cin_k(const float* dh0, const float* attn, float* cin)
{
    int b = blockIdx.x, k = threadIdx.x;
    cin[b*512 + k] = (k < HH) ? dh0[b*HH + k] : attn[b*HH + (k - HH)];
}

// Persistent decoder: 64 steps x 4 layers, one launch. 96 blocks x 256 thr.
__global__ __launch_bounds__(256, 2) void dec_persist_k(
    const float* __restrict__ x, const int* __restrict__ tord,
    const float* __restrict__ cnst, const float* __restrict__ cinAll,
    const float* __restrict__ WeT, const float* __restrict__ WihsT,
    float* __restrict__ H1, float* __restrict__ H2,
    const float* __restrict__ outW, const float* __restrict__ outB,
    const float* __restrict__ Wemb, const float* __restrict__ bemb,
    float* __restrict__ dout)
{
    __shared__ float sE[16][128];
    __shared__ float sIn[16][33];
    __shared__ float sW[32][4][32];
    __shared__ float sRed[16][16];
    __shared__ float sOut[16][4];
    const int tid = threadIdx.x;
    const int tx = tid & 31, ty = tid >> 5;
    const int jc = blockIdx.x & 7;
    const int m0 = (blockIdx.x >> 3)*16, j0 = jc*32;
    const unsigned nb = gridDim.x;
    unsigned round = 0;
    const int tordv = *tord;
    const int j = j0 + tx;
    for (int t = 0; t < 64; t++){
        if (t == 0){
            for (int idx = tid; idx < 16*128; idx += 256){
                int rr = idx >> 7, e = idx & 127;
                int m = m0 + rr;
                const float* xr = x + (((size_t)((m & 63)*TT_ + 63))*GG + (tordv + (m >> 6)))*FF;
                float v = bemb[e] + xr[0]*Wemb[e*4] + xr[1]*Wemb[e*4+1]
                                  + xr[2]*Wemb[e*4+2] + xr[3]*Wemb[e*4+3];
                sE[rr][e] = fmaxf(v, 0.f);
            }
            __syncthreads();
        } else {
            {
                int r = tid >> 4, sub = tid & 15, o = sub & 3, seg = sub >> 2;
                const float* hrow = H2 + (size_t)(m0 + r)*HH;
                float s = 0.f;
                #pragma unroll 4
                for (int h = seg*64; h < seg*64 + 64; h++)
                    s += __ldcg(hrow + h) * outW[o*HH + h];
                sRed[r][sub] = s;
            }
            __syncthreads();
            if (tid < 64){
                int rr = tid >> 2, oo = tid & 3;
                float v = sRed[rr][oo] + sRed[rr][4+oo] + sRed[rr][8+oo] + sRed[rr][12+oo] + outB[oo];
                sOut[rr][oo] = v;
                if (jc == 0){
                    int m = m0 + rr;
                    dout[(size_t)(m & 63)*(TT_*NT*FF) + (size_t)(t-1)*(NT*FF) + (m >> 6)*FF + oo] = v;
                }
            }
            __syncthreads();
            for (int idx = tid; idx < 16*128; idx += 256){
                int rr = idx >> 7, e = idx & 127;
                float v = bemb[e] + sOut[rr][0]*Wemb[e*4] + sOut[rr][1]*Wemb[e*4+1]
                        + sOut[rr][2]*Wemb[e*4+2] + sOut[rr][3]*Wemb[e*4+3];
                sE[rr][e] = fmaxf(v, 0.f);
            }
            __syncthreads();
        }
        for (int l = 0; l < 4; l++){
            float acc[2][4] = {{0.f,0.f,0.f,0.f},{0.f,0.f,0.f,0.f}};
            const float* Wt = (l == 0) ? WeT : (WihsT + (size_t)(l-1)*KSZ);
            const int K = (l == 0) ? EE : HH;
            const float* In = (l == 2) ? H2 : H1;
            float* Ho = (l == 0 || l == 2) ? H1 : H2;
            for (int k0 = 0; k0 < K; k0 += 32){
                if (l > 0 && tid < 128){
                    int r = tid >> 3, kc = (tid & 7)*4;
                    float4 v = __ldcg(reinterpret_cast<const float4*>(In + (size_t)(m0+r)*HH + k0 + kc));
                    sIn[r][kc] = v.x; sIn[r][kc+1] = v.y; sIn[r][kc+2] = v.z; sIn[r][kc+3] = v.w;
                }
                #pragma unroll
                for (int qq = 0; qq < 16; qq++){
                    int lin = qq*256 + tid;
                    int kr = lin >> 7, col = lin & 127;
                    sW[kr][col >> 5][col & 31] =
                        Wt[(size_t)(k0+kr)*NG + (col >> 5)*HH + j0 + (col & 31)];
                }
                __syncthreads();
                #pragma unroll
                for (int kk = 0; kk < 32; kk++){
                    float w0 = sW[kk][0][tx], w1 = sW[kk][1][tx];
                    float w2 = sW[kk][2][tx], w3 = sW[kk][3][tx];
                    float a0 = (l == 0) ? sE[ty*2][k0+kk]   : sIn[ty*2][kk];
                    float a1 = (l == 0) ? sE[ty*2+1][k0+kk] : sIn[ty*2+1][kk];
                    acc[0][0]+=a0*w0; acc[0][1]+=a0*w1; acc[0][2]+=a0*w2; acc[0][3]+=a0*w3;
                    acc[1][0]+=a1*w0; acc[1][1]+=a1*w1; acc[1][2]+=a1*w2; acc[1][3]+=a1*w3;
                }
                __syncthreads();
            }
            const float* cl = cnst + (size_t)l*BB*NG;
            const float* ci = cinAll + (size_t)l*BB*HH;
            #pragma unroll
            for (int rr = 0; rr < 2; rr++){
                int m = m0 + ty*2 + rr, b = m & 63;
                const float* cp = cl + (size_t)b*NG;
                float gi = acc[rr][0] + cp[j];
                float gf = acc[rr][1] + cp[HH + j];
                float gg = acc[rr][2] + cp[2*HH + j];
                float go = acc[rr][3] + cp[3*HH + j];
                float c2 = fsig(gf)*ci[b*HH + j] + fsig(gi)*ftanh(gg);
                Ho[(size_t)m*HH + j] = fsig(go)*ftanh(c2);
            }
            grid_barrier(nb, round);
        }
    }
    {
        int r = tid >> 4, sub = tid & 15, o = sub & 3, seg = sub >> 2;
        const float* hrow = H2 + (size_t)(m0 + r)*HH;
        float s = 0.f;
        #pragma unroll 4
        for (int h = seg*64; h < seg*64 + 64; h++)
            s += __ldcg(hrow + h) * outW[o*HH + h];
        sRed[r][sub] = s;
    }
    __syncthreads();
    if (tid < 64 && jc == 0){
        int rr = tid >> 2, oo = tid & 3;
        float v = sRed[rr][oo] + sRed[rr][4+oo] + sRed[rr][8+oo] + sRed[rr][12+oo] + outB[oo];
        int m = m0 + rr;
        dout[(size_t)(m & 63)*(TT_*NT*FF) + 63u*(NT*FF) + (m >> 6)*FF + oo] = v;
    }
}

static float* symaddr(const void* sym)
{
    void* p = nullptr;
    cudaGetSymbolAddress(&p, sym);
    return (float*)p;
}

extern "C" void kernel_launch(void* const* d_in, const int* in_sizes, int n_in,
                              void* d_out, int out_size)
{
    (void)in_sizes; (void)n_in; (void)out_size;
    const float* x       = (const float*)d_in[0];
    const float* encLinW = (const float*)d_in[2];
    const float* encLinB = (const float*)d_in[3];
    const float* encWih0 = (const float*)d_in[4];
    const float* encWihs = (const float*)d_in[5];
    const float* encWhh  = (const float*)d_in[6];
    const float* encBih  = (const float*)d_in[7];
    const float* encBhh  = (const float*)d_in[8];
    const float* decEmbW = (const float*)d_in[9];
    const float* decEmbB = (const float*)d_in[10];
    const float* attnW   = (const float*)d_in[11];
    const float* decWih0 = (const float*)d_in[13];
    const float* decWihs = (const float*)d_in[14];
    const float* decWhh  = (const float*)d_in[15];
    const float* decBih  = (const float*)d_in[16];
    const float* decBhh  = (const float*)d_in[17];
    const float* outW    = (const float*)d_in[18];
    const float* outB    = (const float*)d_in[19];
    const int*   tord    = (const int*)d_in[20];
    float* out = (float*)d_out;

    float* pX = symaddr(g_X);
    float* pY = symaddr(g_Y0);
    float* pC = symaddr(g_Cst);
    __nv_bfloat16* pAhi = (__nv_bfloat16*)symaddr(g_Ahi);
    __nv_bfloat16* pAlo = (__nv_bfloat16*)symaddr(g_Alo);
    __nv_bfloat16* pWihHi = (__nv_bfloat16*)symaddr(g_WihHi);
    __nv_bfloat16* pWihLo = (__nv_bfloat16*)symaddr(g_WihLo);
    __nv_bfloat16* pWhhHi = (__nv_bfloat16*)symaddr(g_WhhHi);
    __nv_bfloat16* pWhhLo = (__nv_bfloat16*)symaddr(g_WhhLo);
    float* pBiasEncP = symaddr(g_biasEncP);
    float* pDecWihsT = symaddr(g_decWihsT);
    float* pDecWhhT = symaddr(g_decWhhT);
    float* pPack = symaddr(g_WcPack);
    float* pWeT = symaddr(g_decWeT);
    float* pBiasDec = symaddr(g_biasDec);
    float* pDech = symaddr(g_dech);
    float* pDecc = symaddr(g_decc);
    float* pAttn = symaddr(g_attn);
    float* pCin = symaddr(g_cin);
    float* pConst = symaddr(g_const);
    float* pH1 = symaddr(g_h1);
    float* pH2 = symaddr(g_h2);

    cudaFuncSetAttribute(enc_tc_k, cudaFuncAttributeMaxDynamicSharedMemorySize, SMEM_ENC);

    dim3 tb(32, 8);
    wsplit_perm_k<<<(NG*EE + 255)/256, 256>>>(encWih0, EE, pWihHi, pWihLo);
    for (int l = 1; l < 4; l++)
        wsplit_perm_k<<<(NG*HH + 255)/256, 256>>>(encWihs + (size_t)(l-1)*NG*HH, HH,
                                                  pWihHi + NG*EE + (size_t)(l-1)*NG*HH,
                                                  pWihLo + NG*EE + (size_t)(l-1)*NG*HH);
    for (int l = 0; l < 4; l++)
        wsplit_perm_k<<<(NG*HH + 255)/256, 256>>>(encWhh + (size_t)l*NG*HH, HH,
                                                  pWhhHi + (size_t)l*NG*HH,
                                                  pWhhLo + (size_t)l*NG*HH);
    for (int l = 0; l < 4; l++)
        addv_perm_k<<<4, 256>>>(encBih + l*NG, encBhh + l*NG, pBiasEncP + l*NG);
    for (int l = 0; l < 3; l++)
        transpose_k<<<dim3(8, 32), tb>>>(decWihs + (size_t)l*NG*HH, HH, NG, HH, pDecWihsT + (size_t)l*KSZ, NG);
    for (int l = 1; l < 4; l++)
        transpose_k<<<dim3(8, 32), tb>>>(decWhh + (size_t)l*NG*HH, HH, NG, HH, pDecWhhT + (size_t)(l-1)*KSZ, NG);
    transpose_k<<<dim3(8, 32), tb>>>(decWhh, HH, NG, HH, pPack, NG);
    transpose_k<<<dim3(8, 32), tb>>>(decWih0, 384, NG, HH, pPack + (size_t)HH*NG, NG);
    transpose_k<<<dim3(4, 32), tb>>>(decWih0 + HH, 384, NG, EE, pWeT, NG);
    addv_k<<<16, 256>>>(decBih, decBhh, pBiasDec, 4*NG);

    emb_k<<<MTOT, 128>>>(x, encLinW, encLinB, pAhi, pAlo);

    for (int l = 0; l < 4; l++){
        const __nv_bfloat16* wh = (l == 0) ? pWihHi : (pWihHi + NG*EE + (size_t)(l-1)*NG*HH);
        const __nv_bfloat16* wl = (l == 0) ? pWihLo : (pWihLo + NG*EE + (size_t)(l-1)*NG*HH);
        int Kin = (l == 0) ? EE : HH;
        gemm_tc_k<<<dim3(8, MTOT/128), 256>>>(pAhi, pAlo, wh, wl, pBiasEncP + l*NG, pX, Kin);
        reset_barrier_k<<<1, 1>>>();
        enc_tc_k<<<88, 256, SMEM_ENC>>>(pX, pWhhHi + (size_t)l*NG*HH, pWhhLo + (size_t)l*NG*HH,
                                        pY, pC, pAhi, pAlo);
        snap_k<<<64, 256>>>(pY + (size_t)(TT_-1)*GT*HH, pC, tord,
                            pDech + (size_t)l*BB*HH, pDecc + (size_t)l*BB*HH);
    }

    attn_k<<<BB, 256>>>(pY, attnW, pAttn);
    pack_cin_k<<<BB, 512>>>(pDech, pAttn, pCin);
    gemm_k<<<dim3(8, 1), 256>>>(pCin, pPack, pBiasDec, pConst, BB, NG, 512);
    for (int l = 1; l < 4; l++)
        gemm_k<<<dim3(8, 1), 256>>>(pDech + (size_t)l*BB*HH, pDecWhhT + (size_t)(l-1)*KSZ,
                                    pBiasDec + l*NG, pConst + (size_t)l*BB*NG, BB, NG, HH);

    reset_barrier_k<<<1, 1>>>();
    dec_persist_k<<<96, 256>>>(x, tord, pConst, pDecc, pWeT, pDecWihsT,
                               pH1, pH2, outW, outB, decEmbW, decEmbB, out);
}

// round 13
// speedup vs baseline: 1.1620x; 1.0127x over previous
#include <cuda_runtime.h>
#include <cuda_bf16.h>
#include <cstdint>

#define BB   64
#define TT_  64
#define GG   11
#define FF   4
#define HH   256
#define EE   128
#define NT   3
#define GT   (GG*BB)     // 704
#define MTOT (TT_*GT)    // 45056
#define NG   1024
#define KSZ  (256*1024)

// encoder tc persistent tile
#define ER 64
#define EC 128
#define BP 132
#define AP 132
#define SB_WORDS (2*128*BP)
#define SA_WORDS (2*64*AP)
#define SMEM_ENC ((SB_WORDS + SA_WORDS)*4)  // 202752 B

__device__ float g_X[MTOT*NG];
__device__ float g_Y0[MTOT*HH];
__device__ float g_Cst[GT*HH];
__device__ __nv_bfloat16 g_Ahi[MTOT*HH];
__device__ __nv_bfloat16 g_Alo[MTOT*HH];
__device__ __nv_bfloat16 g_WihHi[(EE + 3*HH)*NG];
__device__ __nv_bfloat16 g_WihLo[(EE + 3*HH)*NG];
__device__ __nv_bfloat16 g_WhhHi[4*NG*HH];
__device__ __nv_bfloat16 g_WhhLo[4*NG*HH];
__device__ float g_biasEncP[4*NG];
__device__ float g_decWihsT[3*KSZ];
__device__ float g_decWhhT[3*KSZ];
__device__ float g_WcPack[512*NG];
__device__ float g_decWeT[EE*NG];
__device__ float g_biasDec[4*NG];
__device__ float g_dech[4*BB*HH];
__device__ float g_decc[4*BB*HH];
__device__ float g_attn[BB*HH];
__device__ float g_cin[BB*512];
__device__ float g_const[4*BB*NG];
__device__ float g_h1[NT*BB*HH];
__device__ float g_h2[NT*BB*HH];
__device__ unsigned g_bcnt = 0;
__device__ unsigned g_flag = 0;

__device__ __forceinline__ float ftanh(float x)
{
    float t;
    asm("tanh.approx.f32 %0, %1;" : "=f"(t) : "f"(x));
    return t;
}
__device__ __forceinline__ float fsig(float x)
{
    return fmaf(ftanh(0.5f*x), 0.5f, 0.5f);
}

// fragment-aligned gate permutation:
// n = gate*256 + h ; hp = h>>1, par = h&1, cg = hp>>2, qq = hp&3
// permn = cg*32 + gate*8 + qq*2 + par
// => a thread's 8 accum cols (4 gates x 2) are the complete gate set for 2 h.
__device__ __host__ __forceinline__ int permn(int n)
{
    int gate = n >> 8, h = n & 255;
    int hp = h >> 1, par = h & 1;
    return (hp >> 2)*32 + gate*8 + (hp & 3)*2 + par;
}

__global__ void reset_barrier_k(){ g_bcnt = 0; g_flag = 0; }

__device__ __forceinline__ void grid_barrier(unsigned nb, unsigned& round)
{
    __syncthreads();
    if (threadIdx.x == 0){
        unsigned target = ++round;
        __threadfence();
        unsigned old = atomicAdd(&g_bcnt, 1u);
        if (old == target*nb - 1u){
            asm volatile("st.release.gpu.global.u32 [%0], %1;"
                         :: "l"(&g_flag), "r"(target) : "memory");
            __threadfence();
        } else {
            unsigned v;
            while (true){
                asm volatile("ld.acquire.gpu.global.u32 %0, [%1];"
                             : "=r"(v) : "l"(&g_flag) : "memory");
                if (v >= target) break;
                __nanosleep(32);
            }
        }
    }
    __syncthreads();
}

__global__ void transpose_k(const float* __restrict__ src, int ldS, int rows, int cols,
                            float* __restrict__ dst, int ldD)
{
    __shared__ float tile[32][33];
    int c0 = blockIdx.x*32, r0 = blockIdx.y*32;
    for (int i = threadIdx.y; i < 32; i += 8){
        int r = r0 + i, c = c0 + threadIdx.x;
        tile[i][threadIdx.x] = (r < rows && c < cols) ? src[(size_t)r*ldS + c] : 0.f;
    }
    __syncthreads();
    for (int i = threadIdx.y; i < 32; i += 8){
        int c = c0 + i, r = r0 + threadIdx.x;
        if (c < cols && r < rows) dst[(size_t)c*ldD + r] = tile[threadIdx.x][i];
    }
}

__global__ void addv_k(const float* a, const float* b, float* o, int n)
{
    int i = blockIdx.x*256 + threadIdx.x;
    if (i < n) o[i] = a[i] + b[i];
}

__global__ void addv_perm_k(const float* __restrict__ a, const float* __restrict__ b,
                            float* __restrict__ o)
{
    int n = blockIdx.x*256 + threadIdx.x;
    if (n < NG) o[permn(n)] = a[n] + b[n];
}

__global__ void wsplit_perm_k(const float* __restrict__ src, int K,
                              __nv_bfloat16* __restrict__ hi, __nv_bfloat16* __restrict__ lo)
{
    int i = blockIdx.x*256 + threadIdx.x;
    if (i < NG*K){
        int n = i / K, k = i - n*K;
        float v = src[i];
        __nv_bfloat16 h = __float2bfloat16(v);
        int d = permn(n)*K + k;
        hi[d] = h;
        lo[d] = __float2bfloat16(v - __bfloat162float(h));
    }
}

__global__ void emb_k(const float* __restrict__ x, const float* __restrict__ W,
                      const float* __restrict__ bias,
                      __nv_bfloat16* __restrict__ hi, __nv_bfloat16* __restrict__ lo)
{
    int m = blockIdx.x;
    int t = m / GT; int rem = m % GT; int g = rem >> 6; int b = rem & 63;
    const float* xr = x + (((size_t)(b*TT_ + t))*GG + g)*FF;
    int e = threadIdx.x;
    float v = bias[e] + xr[0]*W[e*4] + xr[1]*W[e*4+1] + xr[2]*W[e*4+2] + xr[3]*W[e*4+3];
    v = fmaxf(v, 0.f);
    __nv_bfloat16 h = __float2bfloat16(v);
    hi[(size_t)m*EE + e] = h;
    lo[(size_t)m*EE + e] = __float2bfloat16(v - __bfloat162float(h));
}

__device__ __forceinline__ void mma_bf16(float* c, const uint32_t* a, uint32_t b0, uint32_t b1)
{
    asm volatile("mma.sync.aligned.m16n8k16.row.col.f32.bf16.bf16.f32 "
        "{%0,%1,%2,%3}, {%4,%5,%6,%7}, {%8,%9}, {%0,%1,%2,%3};"
        : "+f"(c[0]), "+f"(c[1]), "+f"(c[2]), "+f"(c[3])
        : "r"(a[0]), "r"(a[1]), "r"(a[2]), "r"(a[3]), "r"(b0), "r"(b1));
}

// Tensor-core split-bf16 GEMM: C[M][1024] = A[M][K] @ W[1024][K]^T + bias
__global__ __launch_bounds__(256, 2) void gemm_tc_k(
    const __nv_bfloat16* __restrict__ Ahi, const __nv_bfloat16* __restrict__ Alo,
    const __nv_bfloat16* __restrict__ Whi, const __nv_bfloat16* __restrict__ Wlo,
    const float* __restrict__ bias, float* __restrict__ C, int K)
{
    __shared__ __align__(16) uint32_t sA[2][128][20];
    __shared__ __align__(16) uint32_t sB[2][128][20];
    const int tid = threadIdx.x;
    const int lane = tid & 31, wid = tid >> 5;
    const int wm = wid & 3, wn = wid >> 2;
    const int m0 = blockIdx.y*128, n0 = blockIdx.x*128;
    const int g = lane >> 2, q = lane & 3;
    float acc[2][8][4];
    #pragma unroll
    for (int i = 0; i < 2; i++)
        #pragma unroll
        for (int j = 0; j < 8; j++){ acc[i][j][0]=0.f; acc[i][j][1]=0.f; acc[i][j][2]=0.f; acc[i][j][3]=0.f; }

    for (int k0 = 0; k0 < K; k0 += 32){
        #pragma unroll
        for (int rep = 0; rep < 2; rep++){
            int chunk = tid + rep*256;
            int row = chunk >> 2, off = chunk & 3;
            size_t ga = (size_t)(m0 + row)*K + k0 + off*8;
            size_t gb = (size_t)(n0 + row)*K + k0 + off*8;
            *reinterpret_cast<uint4*>(&sA[0][row][off*4]) = *reinterpret_cast<const uint4*>(Ahi + ga);
            *reinterpret_cast<uint4*>(&sA[1][row][off*4]) = *reinterpret_cast<const uint4*>(Alo + ga);
            *reinterpret_cast<uint4*>(&sB[0][row][off*4]) = *reinterpret_cast<const uint4*>(Whi + gb);
            *reinterpret_cast<uint4*>(&sB[1][row][off*4]) = *reinterpret_cast<const uint4*>(Wlo + gb);
        }
        __syncthreads();
        #pragma unroll
        for (int ks = 0; ks < 2; ks++){
            int kp = q + ks*8;
            uint32_t a[2][2][4];
            #pragma unroll
            for (int fm = 0; fm < 2; fm++){
                int row = wm*32 + fm*16;
                #pragma unroll
                for (int s = 0; s < 2; s++){
                    a[fm][s][0] = sA[s][row+g][kp];
                    a[fm][s][1] = sA[s][row+g+8][kp];
                    a[fm][s][2] = sA[s][row+g][kp+4];
                    a[fm][s][3] = sA[s][row+g+8][kp+4];
                }
            }
            #pragma unroll
            for (int fn = 0; fn < 8; fn++){
                int nr = wn*64 + fn*8 + g;
                uint32_t bh0 = sB[0][nr][kp], bh1 = sB[0][nr][kp+4];
                uint32_t bl0 = sB[1][nr][kp], bl1 = sB[1][nr][kp+4];
                #pragma unroll
                for (int fm = 0; fm < 2; fm++){
                    mma_bf16(acc[fm][fn], a[fm][0], bh0, bh1);
                    mma_bf16(acc[fm][fn], a[fm][0], bl0, bl1);
                    mma_bf16(acc[fm][fn], a[fm][1], bh0, bh1);
                }
            }
        }
        __syncthreads();
    }
    #pragma unroll
    for (int fm = 0; fm < 2; fm++){
        int r = m0 + wm*32 + fm*16 + g;
        #pragma unroll
        for (int fn = 0; fn < 8; fn++){
            int cn = n0 + wn*64 + fn*8 + q*2;
            float b0 = bias[cn], b1 = bias[cn+1];
            float2 v0 = make_float2(acc[fm][fn][0] + b0, acc[fm][fn][1] + b1);
            float2 v1 = make_float2(acc[fm][fn][2] + b0, acc[fm][fn][3] + b1);
            *reinterpret_cast<float2*>(C + (size_t)r*NG + cn) = v0;
            *reinterpret_cast<float2*>(C + (size_t)(r+8)*NG + cn) = v1;
        }
    }
}

// fp32 GEMM (decoder constants)
__global__ void gemm_k(const float* __restrict__ A, const float* __restrict__ B,
                       const float* __restrict__ bias, float* __restrict__ C,
                       int M, int N, int K)
{
    __shared__ float As[8][128];
    __shared__ float Bs[8][128];
    int tid = threadIdx.x;
    int m0 = blockIdx.y*128, n0 = blockIdx.x*128;
    int tx = tid & 15, ty = tid >> 4;
    float acc[8][8];
    #pragma unroll
    for (int i = 0; i < 8; i++)
        #pragma unroll
        for (int j = 0; j < 8; j++) acc[i][j] = 0.f;
    int arow = tid >> 1, acol = (tid & 1)*4;
    int brow = tid >> 5, bcol = (tid & 31)*4;
    for (int k0 = 0; k0 < K; k0 += 8){
        float4 av = make_float4(0.f,0.f,0.f,0.f);
        int gm = m0 + arow;
        if (gm < M) av = *reinterpret_cast<const float4*>(A + (size_t)gm*K + k0 + acol);
        As[acol+0][arow] = av.x; As[acol+1][arow] = av.y;
        As[acol+2][arow] = av.z; As[acol+3][arow] = av.w;
        *reinterpret_cast<float4*>(&Bs[brow][bcol]) =
            *reinterpret_cast<const float4*>(B + (size_t)(k0+brow)*N + n0 + bcol);
        __syncthreads();
        #pragma unroll
        for (int kk = 0; kk < 8; kk++){
            float a[8], b[8];
            *reinterpret_cast<float4*>(a)   = *reinterpret_cast<float4*>(&As[kk][ty*4]);
            *reinterpret_cast<float4*>(a+4) = *reinterpret_cast<float4*>(&As[kk][64+ty*4]);
            *reinterpret_cast<float4*>(b)   = *reinterpret_cast<float4*>(&Bs[kk][tx*4]);
            *reinterpret_cast<float4*>(b+4) = *reinterpret_cast<float4*>(&Bs[kk][64+tx*4]);
            #pragma unroll
            for (int i = 0; i < 8; i++)
                #pragma unroll
                for (int j = 0; j < 8; j++) acc[i][j] += a[i]*b[j];
        }
        __syncthreads();
    }
    #pragma unroll
    for (int i = 0; i < 8; i++){
        int gm = m0 + ((i < 4) ? (ty*4 + i) : (64 + ty*4 + (i-4)));
        if (gm >= M) continue;
        #pragma unroll
        for (int j = 0; j < 8; j++){
            int gn = n0 + ((j < 4) ? (tx*4 + j) : (64 + tx*4 + (j-4)));
            C[(size_t)gm*N + gn] = acc[i][j] + bias[gn];
        }
    }
}

// ---------------------------------------------------------------------------
// Persistent tensor-core encoder layer: 64 steps, one launch, 88 blocks.
// Fragment-aligned permutation -> LSTM epilogue straight from mma registers.
// ---------------------------------------------------------------------------
extern __shared__ uint32_t sdyn[];

__global__ void __launch_bounds__(256, 1) enc_tc_k(
    const float* __restrict__ X,
    const __nv_bfloat16* __restrict__ WHi, const __nv_bfloat16* __restrict__ WLo,
    float* __restrict__ Y, float* __restrict__ Cfin,
    __nv_bfloat16* __restrict__ Hhi, __nv_bfloat16* __restrict__ Hlo,
    int writeY)
{
    uint32_t* sB = sdyn;
    uint32_t* sA = sdyn + SB_WORDS;
    const int tid = threadIdx.x;
    const int lane = tid & 31, wid = tid >> 5;
    const int wm = wid & 1, wn = wid >> 1;      // 2 m x 4 n warps
    const int g = lane >> 2, q = lane & 3;
    const int rt = blockIdx.x % 11, ct = blockIdx.x / 11;
    const int m0 = rt*ER, n0 = ct*EC;
    const unsigned nb = gridDim.x;
    unsigned round = 0;

    // load Whh tile once (hi/lo)
    for (int i = tid; i < 2*128*32; i += 256){
        int s = i >> 12;
        int rem = i & 4095;
        int row = rem >> 5, w4 = rem & 31;
        const uint4* src = reinterpret_cast<const uint4*>(
            (s ? WLo : WHi) + (size_t)(n0 + row)*HH) + w4;
        *reinterpret_cast<uint4*>(&sB[s*128*BP + row*BP + w4*4]) = *src;
    }
    __syncthreads();

    // thread's h ownership: h = ct*32 + wn*8 + q*2 + {0,1}
    const int hloc = wn*8 + q*2;
    const int hg = ct*32 + hloc;
    float c[8];
    #pragma unroll
    for (int e = 0; e < 8; e++) c[e] = 0.f;

    for (int t = 0; t < 64; t++){
        float acc[2][4][4];
        #pragma unroll
        for (int i = 0; i < 2; i++)
            #pragma unroll
            for (int j = 0; j < 4; j++){ acc[i][j][0]=0.f; acc[i][j][1]=0.f; acc[i][j][2]=0.f; acc[i][j][3]=0.f; }
        if (t > 0){
            for (int i = tid; i < 2*64*32; i += 256){
                int s = i >> 11;
                int rem = i & 2047;
                int row = rem >> 5, w4 = rem & 31;
                const uint4* src = reinterpret_cast<const uint4*>(
                    (s ? Hlo : Hhi) + ((size_t)(t-1)*GT + m0 + row)*HH) + w4;
                uint4 v = __ldcg(src);
                *reinterpret_cast<uint4*>(&sA[s*64*AP + row*AP + w4*4]) = v;
            }
            __syncthreads();
            #pragma unroll
            for (int ks = 0; ks < 16; ks++){
                const int kp = ks*8 + q;
                uint32_t a[2][2][4];
                #pragma unroll
                for (int fm = 0; fm < 2; fm++){
                    int row = wm*32 + fm*16;
                    #pragma unroll
                    for (int s = 0; s < 2; s++){
                        const uint32_t* base = sA + s*64*AP;
                        a[fm][s][0] = base[(row+g)*AP + kp];
                        a[fm][s][1] = base[(row+g+8)*AP + kp];
                        a[fm][s][2] = base[(row+g)*AP + kp+4];
                        a[fm][s][3] = base[(row+g+8)*AP + kp+4];
                    }
                }
                #pragma unroll
                for (int fn = 0; fn < 4; fn++){
                    int nr = wn*32 + fn*8 + g;
                    uint32_t bh0 = sB[nr*BP + kp], bh1 = sB[nr*BP + kp+4];
                    uint32_t bl0 = sB[128*BP + nr*BP + kp], bl1 = sB[128*BP + nr*BP + kp+4];
                    #pragma unroll
                    for (int fm = 0; fm < 2; fm++){
                        mma_bf16(acc[fm][fn], a[fm][0], bh0, bh1);
                        mma_bf16(acc[fm][fn], a[fm][0], bl0, bl1);
                        mma_bf16(acc[fm][fn], a[fm][1], bh0, bh1);
                    }
                }
            }
        }
        // LSTM epilogue: registers only. Rows wm*32+fm*16+g+rr*8, 2 h each.
        const int doY = (writeY || t == 63);
        #pragma unroll
        for (int fm = 0; fm < 2; fm++){
            #pragma unroll
            for (int rr = 0; rr < 2; rr++){
                int rloc = wm*32 + fm*16 + g + rr*8;
                int rglob = m0 + rloc;
                const float* xp = X + ((size_t)t*GT + rglob)*NG + n0 + wn*32 + q*2;
                float2 xi = *reinterpret_cast<const float2*>(xp);
                float2 xf = *reinterpret_cast<const float2*>(xp + 8);
                float2 xg = *reinterpret_cast<const float2*>(xp + 16);
                float2 xo = *reinterpret_cast<const float2*>(xp + 24);
                int kp = rr*2;
                float gi0 = acc[fm][0][kp]   + xi.x;
                float gi1 = acc[fm][0][kp+1] + xi.y;
                float gf0 = acc[fm][1][kp]   + xf.x;
                float gf1 = acc[fm][1][kp+1] + xf.y;
                float gg0 = acc[fm][2][kp]   + xg.x;
                float gg1 = acc[fm][2][kp+1] + xg.y;
                float go0 = acc[fm][3][kp]   + xo.x;
                float go1 = acc[fm][3][kp+1] + xo.y;
                int ci = fm*4 + rr*2;
                float c0 = fsig(gf0)*c[ci]   + fsig(gi0)*ftanh(gg0);
                float c1 = fsig(gf1)*c[ci+1] + fsig(gi1)*ftanh(gg1);
                c[ci] = c0; c[ci+1] = c1;
                float h0 = fsig(go0)*ftanh(c0);
                float h1 = fsig(go1)*ftanh(c1);
                size_t yb = ((size_t)t*GT + rglob)*HH + hg;
                if (doY) *reinterpret_cast<float2*>(Y + yb) = make_float2(h0, h1);
                __nv_bfloat16 b0 = __float2bfloat16(h0), b1 = __float2bfloat16(h1);
                __nv_bfloat162 hhv; hhv.x = b0; hhv.y = b1;
                __nv_bfloat162 llv;
                llv.x = __float2bfloat16(h0 - __bfloat162float(b0));
                llv.y = __float2bfloat16(h1 - __bfloat162float(b1));
                *reinterpret_cast<__nv_bfloat162*>(Hhi + yb) = hhv;
                *reinterpret_cast<__nv_bfloat162*>(Hlo + yb) = llv;
            }
        }
        grid_barrier(nb, round);
    }
    #pragma unroll
    for (int fm = 0; fm < 2; fm++)
        #pragma unroll
        for (int rr = 0; rr < 2; rr++){
            int rglob = m0 + wm*32 + fm*16 + g + rr*8;
            int ci = fm*4 + rr*2;
            *reinterpret_cast<float2*>(Cfin + (size_t)rglob*HH + hg) =
                make_float2(c[ci], c[ci+1]);
        }
}

__global__ void snap_k(const float* __restrict__ Yt, const float* __restrict__ C,
                       const int* __restrict__ tord, float* dh, float* dc)
{
    int b = blockIdx.x, h = threadIdx.x;
    int row = (*tord)*64 + b;
    dh[b*HH + h] = Yt[(size_t)row*HH + h];
    dc[b*HH + h] = C[(size_t)row*HH + h];
}

__global__ void attn_k(const float* __restrict__ Y3, const float* __restrict__ attnW,
                       float* __restrict__ attn)
{
    int b = blockIdx.x, tid = threadIdx.x;
    __shared__ float wae[HH];
    __shared__ float sc[GT];
    __shared__ float red[256];
    wae[tid] = attnW[HH + tid];
    __syncthreads();
    for (int idx = tid; idx < GT; idx += 256){
        int g = idx % GG, t = idx / GG;
        const float* row = Y3 + ((size_t)(t*GT + g*64 + b))*HH;
        float s = 0.f;
        #pragma unroll 4
        for (int h = 0; h < HH; h++) s += row[h]*wae[h];
        sc[idx] = s;
    }
    __syncthreads();
    float mx = -1e30f;
    for (int idx = tid; idx < GT; idx += 256) mx = fmaxf(mx, sc[idx]);
    red[tid] = mx; __syncthreads();
    for (int s = 128; s > 0; s >>= 1){ if (tid < s) red[tid] = fmaxf(red[tid], red[tid+s]); __syncthreads(); }
    mx = red[0]; __syncthreads();
    float sm = 0.f;
    for (int idx = tid; idx < GT; idx += 256){ float e = __expf(sc[idx]-mx); sc[idx] = e; sm += e; }
    red[tid] = sm; __syncthreads();
    for (int s = 128; s > 0; s >>= 1){ if (tid < s) red[tid] += red[tid+s]; __syncthreads(); }
    float inv = __fdividef(1.f, red[0]);
    __syncthreads();
    float a0 = 0.f;
    for (int idx = 0; idx < GT; idx++){
        int g = idx % GG, t = idx / GG;
        a0 += sc[idx]*Y3[((size_t)(t*GT + g*64 + b))*HH + tid];
    }
    attn[b*HH + tid] = a0*inv;
}

__global__ void pack_cin_k(const float* dh0, const float* attn, float* cin)
{
    int b = blockIdx.x, k = threadIdx.x;
    cin[b*512 + k] = (k < HH) ? dh0[b*HH + k] : attn[b*HH + (k - HH)];
}

// Persistent decoder: 64 steps x 4 layers, one launch. 96 blocks x 256 thr.
__global__ __launch_bounds__(256, 2) void dec_persist_k(
    const float* __restrict__ x, const int* __restrict__ tord,
    const float* __restrict__ cnst, const float* __restrict__ cinAll,
    const float* __restrict__ WeT, const float* __restrict__ WihsT,
    float* __restrict__ H1, float* __restrict__ H2,
    const float* __restrict__ outW, const float* __restrict__ outB,
    const float* __restrict__ Wemb, const float* __restrict__ bemb,
    float* __restrict__ dout)
{
    __shared__ float sE[16][128];
    __shared__ float sIn[16][33];
    __shared__ float sW[32][4][32];
    __shared__ float sRed[16][16];
    __shared__ float sOut[16][4];
    const int tid = threadIdx.x;
    const int tx = tid & 31, ty = tid >> 5;
    const int jc = blockIdx.x & 7;
    const int m0 = (blockIdx.x >> 3)*16, j0 = jc*32;
    const unsigned nb = gridDim.x;
    unsigned round = 0;
    const int tordv = *tord;
    const int j = j0 + tx;
    for (int t = 0; t < 64; t++){
        if (t == 0){
            for (int idx = tid; idx < 16*128; idx += 256){
                int rr = idx >> 7, e = idx & 127;
                int m = m0 + rr;
                const float* xr = x + (((size_t)((m & 63)*TT_ + 63))*GG + (tordv + (m >> 6)))*FF;
                float v = bemb[e] + xr[0]*Wemb[e*4] + xr[1]*Wemb[e*4+1]
                                  + xr[2]*Wemb[e*4+2] + xr[3]*Wemb[e*4+3];
                sE[rr][e] = fmaxf(v, 0.f);
            }
            __syncthreads();
        } else {
            {
                int r = tid >> 4, sub = tid & 15, o = sub & 3, seg = sub >> 2;
                const float* hrow = H2 + (size_t)(m0 + r)*HH;
                float s = 0.f;
                #pragma unroll 4
                for (int h = seg*64; h < seg*64 + 64; h++)
                    s += __ldcg(hrow + h) * outW[o*HH + h];
                sRed[r][sub] = s;
            }
            __syncthreads();
            if (tid < 64){
                int rr = tid >> 2, oo = tid & 3;
                float v = sRed[rr][oo] + sRed[rr][4+oo] + sRed[rr][8+oo] + sRed[rr][12+oo] + outB[oo];
                sOut[rr][oo] = v;
                if (jc == 0){
                    int m = m0 + rr;
                    dout[(size_t)(m & 63)*(TT_*NT*FF) + (size_t)(t-1)*(NT*FF) + (m >> 6)*FF + oo] = v;
                }
            }
            __syncthreads();
            for (int idx = tid; idx < 16*128; idx += 256){
                int rr = idx >> 7, e = idx & 127;
                float v = bemb[e] + sOut[rr][0]*Wemb[e*4] + sOut[rr][1]*Wemb[e*4+1]
                        + sOut[rr][2]*Wemb[e*4+2] + sOut[rr][3]*Wemb[e*4+3];
                sE[rr][e] = fmaxf(v, 0.f);
            }
            __syncthreads();
        }
        for (int l = 0; l < 4; l++){
            float acc[2][4] = {{0.f,0.f,0.f,0.f},{0.f,0.f,0.f,0.f}};
            const float* Wt = (l == 0) ? WeT : (WihsT + (size_t)(l-1)*KSZ);
            const int K = (l == 0) ? EE : HH;
            const float* In = (l == 2) ? H2 : H1;
            float* Ho = (l == 0 || l == 2) ? H1 : H2;
            for (int k0 = 0; k0 < K; k0 += 32){
                if (l > 0 && tid < 128){
                    int r = tid >> 3, kc = (tid & 7)*4;
                    float4 v = __ldcg(reinterpret_cast<const float4*>(In + (size_t)(m0+r)*HH + k0 + kc));
                    sIn[r][kc] = v.x; sIn[r][kc+1] = v.y; sIn[r][kc+2] = v.z; sIn[r][kc+3] = v.w;
                }
                #pragma unroll
                for (int qq = 0; qq < 16; qq++){
                    int lin = qq*256 + tid;
                    int kr = lin >> 7, col = lin & 127;
                    sW[kr][col >> 5][col & 31] =
                        Wt[(size_t)(k0+kr)*NG + (col >> 5)*HH + j0 + (col & 31)];
                }
                __syncthreads();
                #pragma unroll
                for (int kk = 0; kk < 32; kk++){
                    float w0 = sW[kk][0][tx], w1 = sW[kk][1][tx];
                    float w2 = sW[kk][2][tx], w3 = sW[kk][3][tx];
                    float a0 = (l == 0) ? sE[ty*2][k0+kk]   : sIn[ty*2][kk];
                    float a1 = (l == 0) ? sE[ty*2+1][k0+kk] : sIn[ty*2+1][kk];
                    acc[0][0]+=a0*w0; acc[0][1]+=a0*w1; acc[0][2]+=a0*w2; acc[0][3]+=a0*w3;
                    acc[1][0]+=a1*w0; acc[1][1]+=a1*w1; acc[1][2]+=a1*w2; acc[1][3]+=a1*w3;
                }
                __syncthreads();
            }
            const float* cl = cnst + (size_t)l*BB*NG;
            const float* ci = cinAll + (size_t)l*BB*HH;
            #pragma unroll
            for (int rr = 0; rr < 2; rr++){
                int m = m0 + ty*2 + rr, b = m & 63;
                const float* cp = cl + (size_t)b*NG;
                float gi = acc[rr][0] + cp[j];
                float gf = acc[rr][1] + cp[HH + j];
                float gg = acc[rr][2] + cp[2*HH + j];
                float go = acc[rr][3] + cp[3*HH + j];
                float c2 = fsig(gf)*ci[b*HH + j] + fsig(gi)*ftanh(gg);
                Ho[(size_t)m*HH + j] = fsig(go)*ftanh(c2);
            }
            grid_barrier(nb, round);
        }
    }
    {
        int r = tid >> 4, sub = tid & 15, o = sub & 3, seg = sub >> 2;
        const float* hrow = H2 + (size_t)(m0 + r)*HH;
        float s = 0.f;
        #pragma unroll 4
        for (int h = seg*64; h < seg*64 + 64; h++)
            s += __ldcg(hrow + h) * outW[o*HH + h];
        sRed[r][sub] = s;
    }
    __syncthreads();
    if (tid < 64 && jc == 0){
        int rr = tid >> 2, oo = tid & 3;
        float v = sRed[rr][oo] + sRed[rr][4+oo] + sRed[rr][8+oo] + sRed[rr][12+oo] + outB[oo];
        int m = m0 + rr;
        dout[(size_t)(m & 63)*(TT_*NT*FF) + 63u*(NT*FF) + (m >> 6)*FF + oo] = v;
    }
}

static float* symaddr(const void* sym)
{
    void* p = nullptr;
    cudaGetSymbolAddress(&p, sym);
    return (float*)p;
}

extern "C" void kernel_launch(void* const* d_in, const int* in_sizes, int n_in,
                              void* d_out, int out_size)
{
    (void)in_sizes; (void)n_in; (void)out_size;
    const float* x       = (const float*)d_in[0];
    const float* encLinW = (const float*)d_in[2];
    const float* encLinB = (const float*)d_in[3];
    const float* encWih0 = (const float*)d_in[4];
    const float* encWihs = (const float*)d_in[5];
    const float* encWhh  = (const float*)d_in[6];
    const float* encBih  = (const float*)d_in[7];
    const float* encBhh  = (const float*)d_in[8];
    const float* decEmbW = (const float*)d_in[9];
    const float* decEmbB = (const float*)d_in[10];
    const float* attnW   = (const float*)d_in[11];
    const float* decWih0 = (const float*)d_in[13];
    const float* decWihs = (const float*)d_in[14];
    const float* decWhh  = (const float*)d_in[15];
    const float* decBih  = (const float*)d_in[16];
    const float* decBhh  = (const float*)d_in[17];
    const float* outW    = (const float*)d_in[18];
    const float* outB    = (const float*)d_in[19];
    const int*   tord    = (const int*)d_in[20];
    float* out = (float*)d_out;

    float* pX = symaddr(g_X);
    float* pY = symaddr(g_Y0);
    float* pC = symaddr(g_Cst);
    __nv_bfloat16* pAhi = (__nv_bfloat16*)symaddr(g_Ahi);
    __nv_bfloat16* pAlo = (__nv_bfloat16*)symaddr(g_Alo);
    __nv_bfloat16* pWihHi = (__nv_bfloat16*)symaddr(g_WihHi);
    __nv_bfloat16* pWihLo = (__nv_bfloat16*)symaddr(g_WihLo);
    __nv_bfloat16* pWhhHi = (__nv_bfloat16*)symaddr(g_WhhHi);
    __nv_bfloat16* pWhhLo = (__nv_bfloat16*)symaddr(g_WhhLo);
    float* pBiasEncP = symaddr(g_biasEncP);
    float* pDecWihsT = symaddr(g_decWihsT);
    float* pDecWhhT = symaddr(g_decWhhT);
    float* pPack = symaddr(g_WcPack);
    float* pWeT = symaddr(g_decWeT);
    float* pBiasDec = symaddr(g_biasDec);
    float* pDech = symaddr(g_dech);
    float* pDecc = symaddr(g_decc);
    float* pAttn = symaddr(g_attn);
    float* pCin = symaddr(g_cin);
    float* pConst = symaddr(g_const);
    float* pH1 = symaddr(g_h1);
    float* pH2 = symaddr(g_h2);

    cudaFuncSetAttribute(enc_tc_k, cudaFuncAttributeMaxDynamicSharedMemorySize, SMEM_ENC);

    dim3 tb(32, 8);
    wsplit_perm_k<<<(NG*EE + 255)/256, 256>>>(encWih0, EE, pWihHi, pWihLo);
    for (int l = 1; l < 4; l++)
        wsplit_perm_k<<<(NG*HH + 255)/256, 256>>>(encWihs + (size_t)(l-1)*NG*HH, HH,
                                                  pWihHi + NG*EE + (size_t)(l-1)*NG*HH,
                                                  pWihLo + NG*EE + (size_t)(l-1)*NG*HH);
    for (int l = 0; l < 4; l++)
        wsplit_perm_k<<<(NG*HH + 255)/256, 256>>>(encWhh + (size_t)l*NG*HH, HH,
                                                  pWhhHi + (size_t)l*NG*HH,
                                                  pWhhLo + (size_t)l*NG*HH);
    for (int l = 0; l < 4; l++)
        addv_perm_k<<<4, 256>>>(encBih + l*NG, encBhh + l*NG, pBiasEncP + l*NG);
    for (int l = 0; l < 3; l++)
        transpose_k<<<dim3(8, 32), tb>>>(decWihs + (size_t)l*NG*HH, HH, NG, HH, pDecWihsT + (size_t)l*KSZ, NG);
    for (int l = 1; l < 4; l++)
        transpose_k<<<dim3(8, 32), tb>>>(decWhh + (size_t)l*NG*HH, HH, NG, HH, pDecWhhT + (size_t)(l-1)*KSZ, NG);
    transpose_k<<<dim3(8, 32), tb>>>(decWhh, HH, NG, HH, pPack, NG);
    transpose_k<<<dim3(8, 32), tb>>>(decWih0, 384, NG, HH, pPack + (size_t)HH*NG, NG);
    transpose_k<<<dim3(4, 32), tb>>>(decWih0 + HH, 384, NG, EE, pWeT, NG);
    addv_k<<<16, 256>>>(decBih, decBhh, pBiasDec, 4*NG);

    emb_k<<<MTOT, 128>>>(x, encLinW, encLinB, pAhi, pAlo);

    for (int l = 0; l < 4; l++){
        const __nv_bfloat16* wh = (l == 0) ? pWihHi : (pWihHi + NG*EE + (size_t)(l-1)*NG*HH);
        const __nv_bfloat16* wl = (l == 0) ? pWihLo : (pWihLo + NG*EE + (size_t)(l-1)*NG*HH);
        int Kin = (l == 0) ? EE : HH;
        gemm_tc_k<<<dim3(8, MTOT/128), 256>>>(pAhi, pAlo, wh, wl, pBiasEncP + l*NG, pX, Kin);
        reset_barrier_k<<<1, 1>>>();
        enc_tc_k<<<88, 256, SMEM_ENC>>>(pX, pWhhHi + (size_t)l*NG*HH, pWhhLo + (size_t)l*NG*HH,
                                        pY, pC, pAhi, pAlo, (l == 3) ? 1 : 0);
        snap_k<<<64, 256>>>(pY + (size_t)(TT_-1)*GT*HH, pC, tord,
                            pDech + (size_t)l*BB*HH, pDecc + (size_t)l*BB*HH);
    }

    attn_k<<<BB, 256>>>(pY, attnW, pAttn);
    pack_cin_k<<<BB, 512>>>(pDech, pAttn, pCin);
    gemm_k<<<dim3(8, 1), 256>>>(pCin, pPack, pBiasDec, pConst, BB, NG, 512);
    for (int l = 1; l < 4; l++)
        gemm_k<<<dim3(8, 1), 256>>>(pDech + (size_t)l*BB*HH, pDecWhhT + (size_t)(l-1)*KSZ,
                                    pBiasDec + l*NG, pConst + (size_t)l*BB*NG, BB, NG, HH);

    reset_barrier_k<<<1, 1>>>();
    dec_persist_k<<<96, 256>>>(x, tord, pConst, pDecc, pWeT, pDecWihsT,
                               pH1, pH2, outW, outB, decEmbW, decEmbB, out);
}

// round 14
// speedup vs baseline: 1.2496x; 1.0754x over previous
#include <cuda_runtime.h>
#include <cuda_bf16.h>
#include <cstdint>

#define BB   64
#define TT_  64
#define GG   11
#define FF   4
#define HH   256
#define EE   128
#define NT   3
#define GT   (GG*BB)     // 704
#define MTOT (TT_*GT)    // 45056
#define NG   1024
#define KSZ  (256*1024)

// encoder tc persistent tile
#define ER 64
#define EC 128
#define BP 132
#define AP 132
#define SB_WORDS (2*128*BP)
#define SA_WORDS (2*64*AP)
#define SMEM_ENC ((SB_WORDS + SA_WORDS)*4)  // 202752 B

// decoder dynamic smem: sW[2][32][128] + sInF[16][260] + sE[16][128]
#define DW_F   (2*32*128)     // 8192
#define DIN_F  (16*260)       // 4160
#define DE_F   (16*128)       // 2048
#define SMEM_DEC ((DW_F + DIN_F + DE_F)*4)   // 57600 B

__device__ float g_X[MTOT*NG];
__device__ float g_Y0[MTOT*HH];
__device__ float g_Cst[GT*HH];
__device__ __nv_bfloat16 g_Ahi[MTOT*HH];
__device__ __nv_bfloat16 g_Alo[MTOT*HH];
__device__ __nv_bfloat16 g_WihHi[(EE + 3*HH)*NG];
__device__ __nv_bfloat16 g_WihLo[(EE + 3*HH)*NG];
__device__ __nv_bfloat16 g_WhhHi[4*NG*HH];
__device__ __nv_bfloat16 g_WhhLo[4*NG*HH];
__device__ float g_biasEncP[4*NG];
__device__ float g_decWihsT[3*KSZ];
__device__ float g_decWhhT[3*KSZ];
__device__ float g_WcPack[512*NG];
__device__ float g_decWeT[EE*NG];
__device__ float g_biasDec[4*NG];
__device__ float g_dech[4*BB*HH];
__device__ float g_decc[4*BB*HH];
__device__ float g_attn[BB*HH];
__device__ float g_cin[BB*512];
__device__ float g_const[4*BB*NG];
__device__ float g_h1[NT*BB*HH];
__device__ float g_h2[NT*BB*HH];
__device__ unsigned g_bcnt = 0;
__device__ unsigned g_flag = 0;

__device__ __forceinline__ float ftanh(float x)
{
    float t;
    asm("tanh.approx.f32 %0, %1;" : "=f"(t) : "f"(x));
    return t;
}
__device__ __forceinline__ float fsig(float x)
{
    return fmaf(ftanh(0.5f*x), 0.5f, 0.5f);
}

// fragment-aligned gate permutation
__device__ __host__ __forceinline__ int permn(int n)
{
    int gate = n >> 8, h = n & 255;
    int hp = h >> 1, par = h & 1;
    return (hp >> 2)*32 + gate*8 + (hp & 3)*2 + par;
}

__global__ void reset_barrier_k(){ g_bcnt = 0; g_flag = 0; }

__device__ __forceinline__ void grid_barrier(unsigned nb, unsigned& round)
{
    __syncthreads();
    if (threadIdx.x == 0){
        unsigned target = ++round;
        __threadfence();
        unsigned old = atomicAdd(&g_bcnt, 1u);
        if (old == target*nb - 1u){
            asm volatile("st.release.gpu.global.u32 [%0], %1;"
                         :: "l"(&g_flag), "r"(target) : "memory");
            __threadfence();
        } else {
            unsigned v;
            while (true){
                asm volatile("ld.acquire.gpu.global.u32 %0, [%1];"
                             : "=r"(v) : "l"(&g_flag) : "memory");
                if (v >= target) break;
                __nanosleep(32);
            }
        }
    }
    __syncthreads();
}

__global__ void transpose_k(const float* __restrict__ src, int ldS, int rows, int cols,
                            float* __restrict__ dst, int ldD)
{
    __shared__ float tile[32][33];
    int c0 = blockIdx.x*32, r0 = blockIdx.y*32;
    for (int i = threadIdx.y; i < 32; i += 8){
        int r = r0 + i, c = c0 + threadIdx.x;
        tile[i][threadIdx.x] = (r < rows && c < cols) ? src[(size_t)r*ldS + c] : 0.f;
    }
    __syncthreads();
    for (int i = threadIdx.y; i < 32; i += 8){
        int c = c0 + i, r = r0 + threadIdx.x;
        if (c < cols && r < rows) dst[(size_t)c*ldD + r] = tile[threadIdx.x][i];
    }
}

__global__ void addv_k(const float* a, const float* b, float* o, int n)
{
    int i = blockIdx.x*256 + threadIdx.x;
    if (i < n) o[i] = a[i] + b[i];
}

__global__ void addv_perm_k(const float* __restrict__ a, const float* __restrict__ b,
                            float* __restrict__ o)
{
    int n = blockIdx.x*256 + threadIdx.x;
    if (n < NG) o[permn(n)] = a[n] + b[n];
}

__global__ void wsplit_perm_k(const float* __restrict__ src, int K,
                              __nv_bfloat16* __restrict__ hi, __nv_bfloat16* __restrict__ lo)
{
    int i = blockIdx.x*256 + threadIdx.x;
    if (i < NG*K){
        int n = i / K, k = i - n*K;
        float v = src[i];
        __nv_bfloat16 h = __float2bfloat16(v);
        int d = permn(n)*K + k;
        hi[d] = h;
        lo[d] = __float2bfloat16(v - __bfloat162float(h));
    }
}

__global__ void emb_k(const float* __restrict__ x, const float* __restrict__ W,
                      const float* __restrict__ bias,
                      __nv_bfloat16* __restrict__ hi, __nv_bfloat16* __restrict__ lo)
{
    int m = blockIdx.x;
    int t = m / GT; int rem = m % GT; int g = rem >> 6; int b = rem & 63;
    const float* xr = x + (((size_t)(b*TT_ + t))*GG + g)*FF;
    int e = threadIdx.x;
    float v = bias[e] + xr[0]*W[e*4] + xr[1]*W[e*4+1] + xr[2]*W[e*4+2] + xr[3]*W[e*4+3];
    v = fmaxf(v, 0.f);
    __nv_bfloat16 h = __float2bfloat16(v);
    hi[(size_t)m*EE + e] = h;
    lo[(size_t)m*EE + e] = __float2bfloat16(v - __bfloat162float(h));
}

__device__ __forceinline__ void mma_bf16(float* c, const uint32_t* a, uint32_t b0, uint32_t b1)
{
    asm volatile("mma.sync.aligned.m16n8k16.row.col.f32.bf16.bf16.f32 "
        "{%0,%1,%2,%3}, {%4,%5,%6,%7}, {%8,%9}, {%0,%1,%2,%3};"
        : "+f"(c[0]), "+f"(c[1]), "+f"(c[2]), "+f"(c[3])
        : "r"(a[0]), "r"(a[1]), "r"(a[2]), "r"(a[3]), "r"(b0), "r"(b1));
}

// Tensor-core split-bf16 GEMM: C[M][1024] = A[M][K] @ W[1024][K]^T + bias
__global__ __launch_bounds__(256, 2) void gemm_tc_k(
    const __nv_bfloat16* __restrict__ Ahi, const __nv_bfloat16* __restrict__ Alo,
    const __nv_bfloat16* __restrict__ Whi, const __nv_bfloat16* __restrict__ Wlo,
    const float* __restrict__ bias, float* __restrict__ C, int K)
{
    __shared__ __align__(16) uint32_t sA[2][128][20];
    __shared__ __align__(16) uint32_t sB[2][128][20];
    const int tid = threadIdx.x;
    const int lane = tid & 31, wid = tid >> 5;
    const int wm = wid & 3, wn = wid >> 2;
    const int m0 = blockIdx.y*128, n0 = blockIdx.x*128;
    const int g = lane >> 2, q = lane & 3;
    float acc[2][8][4];
    #pragma unroll
    for (int i = 0; i < 2; i++)
        #pragma unroll
        for (int j = 0; j < 8; j++){ acc[i][j][0]=0.f; acc[i][j][1]=0.f; acc[i][j][2]=0.f; acc[i][j][3]=0.f; }

    for (int k0 = 0; k0 < K; k0 += 32){
        #pragma unroll
        for (int rep = 0; rep < 2; rep++){
            int chunk = tid + rep*256;
            int row = chunk >> 2, off = chunk & 3;
            size_t ga = (size_t)(m0 + row)*K + k0 + off*8;
            size_t gb = (size_t)(n0 + row)*K + k0 + off*8;
            *reinterpret_cast<uint4*>(&sA[0][row][off*4]) = *reinterpret_cast<const uint4*>(Ahi + ga);
            *reinterpret_cast<uint4*>(&sA[1][row][off*4]) = *reinterpret_cast<const uint4*>(Alo + ga);
            *reinterpret_cast<uint4*>(&sB[0][row][off*4]) = *reinterpret_cast<const uint4*>(Whi + gb);
            *reinterpret_cast<uint4*>(&sB[1][row][off*4]) = *reinterpret_cast<const uint4*>(Wlo + gb);
        }
        __syncthreads();
        #pragma unroll
        for (int ks = 0; ks < 2; ks++){
            int kp = q + ks*8;
            uint32_t a[2][2][4];
            #pragma unroll
            for (int fm = 0; fm < 2; fm++){
                int row = wm*32 + fm*16;
                #pragma unroll
                for (int s = 0; s < 2; s++){
                    a[fm][s][0] = sA[s][row+g][kp];
                    a[fm][s][1] = sA[s][row+g+8][kp];
                    a[fm][s][2] = sA[s][row+g][kp+4];
                    a[fm][s][3] = sA[s][row+g+8][kp+4];
                }
            }
            #pragma unroll
            for (int fn = 0; fn < 8; fn++){
                int nr = wn*64 + fn*8 + g;
                uint32_t bh0 = sB[0][nr][kp], bh1 = sB[0][nr][kp+4];
                uint32_t bl0 = sB[1][nr][kp], bl1 = sB[1][nr][kp+4];
                #pragma unroll
                for (int fm = 0; fm < 2; fm++){
                    mma_bf16(acc[fm][fn], a[fm][0], bh0, bh1);
                    mma_bf16(acc[fm][fn], a[fm][0], bl0, bl1);
                    mma_bf16(acc[fm][fn], a[fm][1], bh0, bh1);
                }
            }
        }
        __syncthreads();
    }
    #pragma unroll
    for (int fm = 0; fm < 2; fm++){
        int r = m0 + wm*32 + fm*16 + g;
        #pragma unroll
        for (int fn = 0; fn < 8; fn++){
            int cn = n0 + wn*64 + fn*8 + q*2;
            float b0 = bias[cn], b1 = bias[cn+1];
            float2 v0 = make_float2(acc[fm][fn][0] + b0, acc[fm][fn][1] + b1);
            float2 v1 = make_float2(acc[fm][fn][2] + b0, acc[fm][fn][3] + b1);
            *reinterpret_cast<float2*>(C + (size_t)r*NG + cn) = v0;
            *reinterpret_cast<float2*>(C + (size_t)(r+8)*NG + cn) = v1;
        }
    }
}

// fp32 GEMM (decoder constants)
__global__ void gemm_k(const float* __restrict__ A, const float* __restrict__ B,
                       const float* __restrict__ bias, float* __restrict__ C,
                       int M, int N, int K)
{
    __shared__ float As[8][128];
    __shared__ float Bs[8][128];
    int tid = threadIdx.x;
    int m0 = blockIdx.y*128, n0 = blockIdx.x*128;
    int tx = tid & 15, ty = tid >> 4;
    float acc[8][8];
    #pragma unroll
    for (int i = 0; i < 8; i++)
        #pragma unroll
        for (int j = 0; j < 8; j++) acc[i][j] = 0.f;
    int arow = tid >> 1, acol = (tid & 1)*4;
    int brow = tid >> 5, bcol = (tid & 31)*4;
    for (int k0 = 0; k0 < K; k0 += 8){
        float4 av = make_float4(0.f,0.f,0.f,0.f);
        int gm = m0 + arow;
        if (gm < M) av = *reinterpret_cast<const float4*>(A + (size_t)gm*K + k0 + acol);
        As[acol+0][arow] = av.x; As[acol+1][arow] = av.y;
        As[acol+2][arow] = av.z; As[acol+3][arow] = av.w;
        *reinterpret_cast<float4*>(&Bs[brow][bcol]) =
            *reinterpret_cast<const float4*>(B + (size_t)(k0+brow)*N + n0 + bcol);
        __syncthreads();
        #pragma unroll
        for (int kk = 0; kk < 8; kk++){
            float a[8], b[8];
            *reinterpret_cast<float4*>(a)   = *reinterpret_cast<float4*>(&As[kk][ty*4]);
            *reinterpret_cast<float4*>(a+4) = *reinterpret_cast<float4*>(&As[kk][64+ty*4]);
            *reinterpret_cast<float4*>(b)   = *reinterpret_cast<float4*>(&Bs[kk][tx*4]);
            *reinterpret_cast<float4*>(b+4) = *reinterpret_cast<float4*>(&Bs[kk][64+tx*4]);
            #pragma unroll
            for (int i = 0; i < 8; i++)
                #pragma unroll
                for (int j = 0; j < 8; j++) acc[i][j] += a[i]*b[j];
        }
        __syncthreads();
    }
    #pragma unroll
    for (int i = 0; i < 8; i++){
        int gm = m0 + ((i < 4) ? (ty*4 + i) : (64 + ty*4 + (i-4)));
        if (gm >= M) continue;
        #pragma unroll
        for (int j = 0; j < 8; j++){
            int gn = n0 + ((j < 4) ? (tx*4 + j) : (64 + tx*4 + (j-4)));
            C[(size_t)gm*N + gn] = acc[i][j] + bias[gn];
        }
    }
}

// ---------------------------------------------------------------------------
// Persistent tensor-core encoder layer: 64 steps, one launch, 88 blocks.
// X gate values prefetched into registers at step start (before mma).
// ---------------------------------------------------------------------------
extern __shared__ uint32_t sdyn[];

__global__ void __launch_bounds__(256, 1) enc_tc_k(
    const float* __restrict__ X,
    const __nv_bfloat16* __restrict__ WHi, const __nv_bfloat16* __restrict__ WLo,
    float* __restrict__ Y, float* __restrict__ Cfin,
    __nv_bfloat16* __restrict__ Hhi, __nv_bfloat16* __restrict__ Hlo,
    int writeY)
{
    uint32_t* sB = sdyn;
    uint32_t* sA = sdyn + SB_WORDS;
    const int tid = threadIdx.x;
    const int lane = tid & 31, wid = tid >> 5;
    const int wm = wid & 1, wn = wid >> 1;
    const int g = lane >> 2, q = lane & 3;
    const int rt = blockIdx.x % 11, ct = blockIdx.x / 11;
    const int m0 = rt*ER, n0 = ct*EC;
    const unsigned nb = gridDim.x;
    unsigned round = 0;

    for (int i = tid; i < 2*128*32; i += 256){
        int s = i >> 12;
        int rem = i & 4095;
        int row = rem >> 5, w4 = rem & 31;
        const uint4* src = reinterpret_cast<const uint4*>(
            (s ? WLo : WHi) + (size_t)(n0 + row)*HH) + w4;
        *reinterpret_cast<uint4*>(&sB[s*128*BP + row*BP + w4*4]) = *src;
    }
    __syncthreads();

    const int hloc = wn*8 + q*2;
    const int hg = ct*32 + hloc;
    float c[8];
    #pragma unroll
    for (int e = 0; e < 8; e++) c[e] = 0.f;

    for (int t = 0; t < 64; t++){
        // prefetch X gate values for this step (ready since gemm_tc)
        float2 xv[2][2][4];
        #pragma unroll
        for (int fm = 0; fm < 2; fm++)
            #pragma unroll
            for (int rr = 0; rr < 2; rr++){
                int rglob = m0 + wm*32 + fm*16 + g + rr*8;
                const float* xp = X + ((size_t)t*GT + rglob)*NG + n0 + wn*32 + q*2;
                xv[fm][rr][0] = __ldcg(reinterpret_cast<const float2*>(xp));
                xv[fm][rr][1] = __ldcg(reinterpret_cast<const float2*>(xp + 8));
                xv[fm][rr][2] = __ldcg(reinterpret_cast<const float2*>(xp + 16));
                xv[fm][rr][3] = __ldcg(reinterpret_cast<const float2*>(xp + 24));
            }
        float acc[2][4][4];
        #pragma unroll
        for (int i = 0; i < 2; i++)
            #pragma unroll
            for (int j = 0; j < 4; j++){ acc[i][j][0]=0.f; acc[i][j][1]=0.f; acc[i][j][2]=0.f; acc[i][j][3]=0.f; }
        if (t > 0){
            for (int i = tid; i < 2*64*32; i += 256){
                int s = i >> 11;
                int rem = i & 2047;
                int row = rem >> 5, w4 = rem & 31;
                const uint4* src = reinterpret_cast<const uint4*>(
                    (s ? Hlo : Hhi) + ((size_t)(t-1)*GT + m0 + row)*HH) + w4;
                uint4 v = __ldcg(src);
                *reinterpret_cast<uint4*>(&sA[s*64*AP + row*AP + w4*4]) = v;
            }
            __syncthreads();
            #pragma unroll
            for (int ks = 0; ks < 16; ks++){
                const int kp = ks*8 + q;
                uint32_t a[2][2][4];
                #pragma unroll
                for (int fm = 0; fm < 2; fm++){
                    int row = wm*32 + fm*16;
                    #pragma unroll
                    for (int s = 0; s < 2; s++){
                        const uint32_t* base = sA + s*64*AP;
                        a[fm][s][0] = base[(row+g)*AP + kp];
                        a[fm][s][1] = base[(row+g+8)*AP + kp];
                        a[fm][s][2] = base[(row+g)*AP + kp+4];
                        a[fm][s][3] = base[(row+g+8)*AP + kp+4];
                    }
                }
                #pragma unroll
                for (int fn = 0; fn < 4; fn++){
                    int nr = wn*32 + fn*8 + g;
                    uint32_t bh0 = sB[nr*BP + kp], bh1 = sB[nr*BP + kp+4];
                    uint32_t bl0 = sB[128*BP + nr*BP + kp], bl1 = sB[128*BP + nr*BP + kp+4];
                    #pragma unroll
                    for (int fm = 0; fm < 2; fm++){
                        mma_bf16(acc[fm][fn], a[fm][0], bh0, bh1);
                        mma_bf16(acc[fm][fn], a[fm][0], bl0, bl1);
                        mma_bf16(acc[fm][fn], a[fm][1], bh0, bh1);
                    }
                }
            }
        }
        const int doY = (writeY || t == 63);
        #pragma unroll
        for (int fm = 0; fm < 2; fm++){
            #pragma unroll
            for (int rr = 0; rr < 2; rr++){
                int rglob = m0 + wm*32 + fm*16 + g + rr*8;
                int kp = rr*2;
                float gi0 = acc[fm][0][kp]   + xv[fm][rr][0].x;
                float gi1 = acc[fm][0][kp+1] + xv[fm][rr][0].y;
                float gf0 = acc[fm][1][kp]   + xv[fm][rr][1].x;
                float gf1 = acc[fm][1][kp+1] + xv[fm][rr][1].y;
                float gg0 = acc[fm][2][kp]   + xv[fm][rr][2].x;
                float gg1 = acc[fm][2][kp+1] + xv[fm][rr][2].y;
                float go0 = acc[fm][3][kp]   + xv[fm][rr][3].x;
                float go1 = acc[fm][3][kp+1] + xv[fm][rr][3].y;
                int ci = fm*4 + rr*2;
                float c0 = fsig(gf0)*c[ci]   + fsig(gi0)*ftanh(gg0);
                float c1 = fsig(gf1)*c[ci+1] + fsig(gi1)*ftanh(gg1);
                c[ci] = c0; c[ci+1] = c1;
                float h0 = fsig(go0)*ftanh(c0);
                float h1 = fsig(go1)*ftanh(c1);
                size_t yb = ((size_t)t*GT + rglob)*HH + hg;
                if (doY) *reinterpret_cast<float2*>(Y + yb) = make_float2(h0, h1);
                __nv_bfloat16 b0 = __float2bfloat16(h0), b1 = __float2bfloat16(h1);
                __nv_bfloat162 hhv; hhv.x = b0; hhv.y = b1;
                __nv_bfloat162 llv;
                llv.x = __float2bfloat16(h0 - __bfloat162float(b0));
                llv.y = __float2bfloat16(h1 - __bfloat162float(b1));
                *reinterpret_cast<__nv_bfloat162*>(Hhi + yb) = hhv;
                *reinterpret_cast<__nv_bfloat162*>(Hlo + yb) = llv;
            }
        }
        grid_barrier(nb, round);
    }
    #pragma unroll
    for (int fm = 0; fm < 2; fm++)
        #pragma unroll
        for (int rr = 0; rr < 2; rr++){
            int rglob = m0 + wm*32 + fm*16 + g + rr*8;
            int ci = fm*4 + rr*2;
            *reinterpret_cast<float2*>(Cfin + (size_t)rglob*HH + hg) =
                make_float2(c[ci], c[ci+1]);
        }
}

__global__ void snap_k(const float* __restrict__ Yt, const float* __restrict__ C,
                       const int* __restrict__ tord, float* dh, float* dc)
{
    int b = blockIdx.x, h = threadIdx.x;
    int row = (*tord)*64 + b;
    dh[b*HH + h] = Yt[(size_t)row*HH + h];
    dc[b*HH + h] = C[(size_t)row*HH + h];
}

__global__ void attn_k(const float* __restrict__ Y3, const float* __restrict__ attnW,
                       float* __restrict__ attn)
{
    int b = blockIdx.x, tid = threadIdx.x;
    __shared__ float wae[HH];
    __shared__ float sc[GT];
    __shared__ float red[256];
    wae[tid] = attnW[HH + tid];
    __syncthreads();
    for (int idx = tid; idx < GT; idx += 256){
        int g = idx % GG, t = idx / GG;
        const float* row = Y3 + ((size_t)(t*GT + g*64 + b))*HH;
        float s = 0.f;
        #pragma unroll 4
        for (int h = 0; h < HH; h++) s += row[h]*wae[h];
        sc[idx] = s;
    }
    __syncthreads();
    float mx = -1e30f;
    for (int idx = tid; idx < GT; idx += 256) mx = fmaxf(mx, sc[idx]);
    red[tid] = mx; __syncthreads();
    for (int s = 128; s > 0; s >>= 1){ if (tid < s) red[tid] = fmaxf(red[tid], red[tid+s]); __syncthreads(); }
    mx = red[0]; __syncthreads();
    float sm = 0.f;
    for (int idx = tid; idx < GT; idx += 256){ float e = __expf(sc[idx]-mx); sc[idx] = e; sm += e; }
    red[tid] = sm; __syncthreads();
    for (int s = 128; s > 0; s >>= 1){ if (tid < s) red[tid] += red[tid+s]; __syncthreads(); }
    float inv = __fdividef(1.f, red[0]);
    __syncthreads();
    float a0 = 0.f;
    for (int idx = 0; idx < GT; idx++){
        int g = idx % GG, t = idx / GG;
        a0 += sc[idx]*Y3[((size_t)(t*GT + g*64 + b))*HH + tid];
    }
    attn[b*HH + tid] = a0*inv;
}

__global__ void pack_cin_k(const float* dh0, const float* attn, float* cin)
{
    int b = blockIdx.x, k = threadIdx.x;
    cin[b*512 + k] = (k < HH) ? dh0[b*HH + k] : attn[b*HH + (k - HH)];
}

// ---------------------------------------------------------------------------
// Persistent decoder: 64 steps x 4 layers, one launch. 96 blocks x 256 thr.
// Double-buffered weight staging (register prefetch), full In staged per phase.
// Dynamic smem: sW[2][32][128] | sInF[16][260] | sE[16][128]
// ---------------------------------------------------------------------------
__global__ __launch_bounds__(256, 2) void dec_persist_k(
    const float* __restrict__ x, const int* __restrict__ tord,
    const float* __restrict__ cnst, const float* __restrict__ cinAll,
    const float* __restrict__ WeT, const float* __restrict__ WihsT,
    float* __restrict__ H1, float* __restrict__ H2,
    const float* __restrict__ outW, const float* __restrict__ outB,
    const float* __restrict__ Wemb, const float* __restrict__ bemb,
    float* __restrict__ dout)
{
    float* sW   = reinterpret_cast<float*>(sdyn);       // [2][32][128]
    float* sInF = sW + DW_F;                            // [16][260]
    float* sE   = sInF + DIN_F;                         // [16][128]
    __shared__ float sRed[16][16];
    __shared__ float sOut[16][4];
    const int tid = threadIdx.x;
    const int tx = tid & 31, ty = tid >> 5;
    const int jc = blockIdx.x & 7;
    const int m0 = (blockIdx.x >> 3)*16, j0 = jc*32;
    const unsigned nb = gridDim.x;
    unsigned round = 0;
    const int tordv = *tord;
    const int j = j0 + tx;
    // weight-staging lane constants: i = r*256+tid -> row=i>>5, c4=i&31
    const int wrow = tid >> 5, wc4 = tid & 31;   // r adds 8 to row per step of 256
    const size_t wcol = (size_t)(wc4 >> 3)*HH + j0 + (wc4 & 7)*4;

    for (int t = 0; t < 64; t++){
        if (t == 0){
            for (int idx = tid; idx < 16*128; idx += 256){
                int rr = idx >> 7, e = idx & 127;
                int m = m0 + rr;
                const float* xr = x + (((size_t)((m & 63)*TT_ + 63))*GG + (tordv + (m >> 6)))*FF;
                float v = bemb[e] + xr[0]*Wemb[e*4] + xr[1]*Wemb[e*4+1]
                                  + xr[2]*Wemb[e*4+2] + xr[3]*Wemb[e*4+3];
                sE[rr*128 + e] = fmaxf(v, 0.f);
            }
            __syncthreads();
        } else {
            {
                int r = tid >> 4, sub = tid & 15, o = sub & 3, seg = sub >> 2;
                const float* hrow = H2 + (size_t)(m0 + r)*HH;
                float s = 0.f;
                #pragma unroll 4
                for (int h = seg*64; h < seg*64 + 64; h++)
                    s += __ldcg(hrow + h) * outW[o*HH + h];
                sRed[r][sub] = s;
            }
            __syncthreads();
            if (tid < 64){
                int rr = tid >> 2, oo = tid & 3;
                float v = sRed[rr][oo] + sRed[rr][4+oo] + sRed[rr][8+oo] + sRed[rr][12+oo] + outB[oo];
                sOut[rr][oo] = v;
                if (jc == 0){
                    int m = m0 + rr;
                    dout[(size_t)(m & 63)*(TT_*NT*FF) + (size_t)(t-1)*(NT*FF) + (m >> 6)*FF + oo] = v;
                }
            }
            __syncthreads();
            for (int idx = tid; idx < 16*128; idx += 256){
                int rr = idx >> 7, e = idx & 127;
                float v = bemb[e] + sOut[rr][0]*Wemb[e*4] + sOut[rr][1]*Wemb[e*4+1]
                        + sOut[rr][2]*Wemb[e*4+2] + sOut[rr][3]*Wemb[e*4+3];
                sE[rr*128 + e] = fmaxf(v, 0.f);
            }
            __syncthreads();
        }
        for (int l = 0; l < 4; l++){
            const float* Wt = (l == 0) ? WeT : (WihsT + (size_t)(l-1)*KSZ);
            const int K = (l == 0) ? EE : HH;
            const int nch = K >> 5;
            const float* In = (l == 2) ? H2 : H1;
            float* Ho = (l == 0 || l == 2) ? H1 : H2;
            // prefetch weight chunk 0 + stage full In
            float4 wreg[4];
            #pragma unroll
            for (int r = 0; r < 4; r++)
                wreg[r] = __ldcg(reinterpret_cast<const float4*>(
                    Wt + (size_t)(wrow + r*8)*NG + wcol));
            if (l > 0){
                #pragma unroll
                for (int r = 0; r < 4; r++){
                    int i = r*256 + tid, row = i >> 6, c4 = i & 63;
                    float4 v = __ldcg(reinterpret_cast<const float4*>(
                        In + (size_t)(m0 + row)*HH + c4*4));
                    *reinterpret_cast<float4*>(&sInF[row*260 + c4*4]) = v;
                }
            }
            #pragma unroll
            for (int r = 0; r < 4; r++)
                *reinterpret_cast<float4*>(&sW[(wrow + r*8)*128 + wc4*4]) = wreg[r];
            __syncthreads();
            float acc[2][4] = {{0.f,0.f,0.f,0.f},{0.f,0.f,0.f,0.f}};
            const float* aIn = (l == 0) ? sE : sInF;
            const int aPitch = (l == 0) ? 128 : 260;
            for (int ch = 0; ch < nch; ch++){
                if (ch + 1 < nch){
                    #pragma unroll
                    for (int r = 0; r < 4; r++)
                        wreg[r] = __ldcg(reinterpret_cast<const float4*>(
                            Wt + (size_t)((ch+1)*32 + wrow + r*8)*NG + wcol));
                }
                const float* wb = sW + (size_t)(ch & 1)*32*128;
                const float* a0p = aIn + (ty*2)*aPitch + ch*32;
                const float* a1p = aIn + (ty*2+1)*aPitch + ch*32;
                #pragma unroll
                for (int kk = 0; kk < 32; kk++){
                    const float* wr = wb + kk*128;
                    float w0 = wr[tx], w1 = wr[32+tx], w2 = wr[64+tx], w3 = wr[96+tx];
                    float a0 = a0p[kk], a1 = a1p[kk];
                    acc[0][0]+=a0*w0; acc[0][1]+=a0*w1; acc[0][2]+=a0*w2; acc[0][3]+=a0*w3;
                    acc[1][0]+=a1*w0; acc[1][1]+=a1*w1; acc[1][2]+=a1*w2; acc[1][3]+=a1*w3;
                }
                if (ch + 1 < nch){
                    #pragma unroll
                    for (int r = 0; r < 4; r++)
                        *reinterpret_cast<float4*>(&sW[((ch+1)&1)*32*128 + (wrow + r*8)*128 + wc4*4]) = wreg[r];
                    __syncthreads();
                }
            }
            const float* cl = cnst + (size_t)l*BB*NG;
            const float* ci = cinAll + (size_t)l*BB*HH;
            #pragma unroll
            for (int rr = 0; rr < 2; rr++){
                int m = m0 + ty*2 + rr, b = m & 63;
                const float* cp = cl + (size_t)b*NG;
                float gi = acc[rr][0] + cp[j];
                float gf = acc[rr][1] + cp[HH + j];
                float gg = acc[rr][2] + cp[2*HH + j];
                float go = acc[rr][3] + cp[3*HH + j];
                float c2 = fsig(gf)*ci[b*HH + j] + fsig(gi)*ftanh(gg);
                Ho[(size_t)m*HH + j] = fsig(go)*ftanh(c2);
            }
            grid_barrier(nb, round);
        }
    }
    {
        int r = tid >> 4, sub = tid & 15, o = sub & 3, seg = sub >> 2;
        const float* hrow = H2 + (size_t)(m0 + r)*HH;
        float s = 0.f;
        #pragma unroll 4
        for (int h = seg*64; h < seg*64 + 64; h++)
            s += __ldcg(hrow + h) * outW[o*HH + h];
        sRed[r][sub] = s;
    }
    __syncthreads();
    if (tid < 64 && jc == 0){
        int rr = tid >> 2, oo = tid & 3;
        float v = sRed[rr][oo] + sRed[rr][4+oo] + sRed[rr][8+oo] + sRed[rr][12+oo] + outB[oo];
        int m = m0 + rr;
        dout[(size_t)(m & 63)*(TT_*NT*FF) + 63u*(NT*FF) + (m >> 6)*FF + oo] = v;
    }
}

static float* symaddr(const void* sym)
{
    void* p = nullptr;
    cudaGetSymbolAddress(&p, sym);
    return (float*)p;
}

extern "C" void kernel_launch(void* const* d_in, const int* in_sizes, int n_in,
                              void* d_out, int out_size)
{
    (void)in_sizes; (void)n_in; (void)out_size;
    const float* x       = (const float*)d_in[0];
    const float* encLinW = (const float*)d_in[2];
    const float* encLinB = (const float*)d_in[3];
    const float* encWih0 = (const float*)d_in[4];
    const float* encWihs = (const float*)d_in[5];
    const float* encWhh  = (const float*)d_in[6];
    const float* encBih  = (const float*)d_in[7];
    const float* encBhh  = (const float*)d_in[8];
    const float* decEmbW = (const float*)d_in[9];
    const float* decEmbB = (const float*)d_in[10];
    const float* attnW   = (const float*)d_in[11];
    const float* decWih0 = (const float*)d_in[13];
    const float* decWihs = (const float*)d_in[14];
    const float* decWhh  = (const float*)d_in[15];
    const float* decBih  = (const float*)d_in[16];
    const float* decBhh  = (const float*)d_in[17];
    const float* outW    = (const float*)d_in[18];
    const float* outB    = (const float*)d_in[19];
    const int*   tord    = (const int*)d_in[20];
    float* out = (float*)d_out;

    float* pX = symaddr(g_X);
    float* pY = symaddr(g_Y0);
    float* pC = symaddr(g_Cst);
    __nv_bfloat16* pAhi = (__nv_bfloat16*)symaddr(g_Ahi);
    __nv_bfloat16* pAlo = (__nv_bfloat16*)symaddr(g_Alo);
    __nv_bfloat16* pWihHi = (__nv_bfloat16*)symaddr(g_WihHi);
    __nv_bfloat16* pWihLo = (__nv_bfloat16*)symaddr(g_WihLo);
    __nv_bfloat16* pWhhHi = (__nv_bfloat16*)symaddr(g_WhhHi);
    __nv_bfloat16* pWhhLo = (__nv_bfloat16*)symaddr(g_WhhLo);
    float* pBiasEncP = symaddr(g_biasEncP);
    float* pDecWihsT = symaddr(g_decWihsT);
    float* pDecWhhT = symaddr(g_decWhhT);
    float* pPack = symaddr(g_WcPack);
    float* pWeT = symaddr(g_decWeT);
    float* pBiasDec = symaddr(g_biasDec);
    float* pDech = symaddr(g_dech);
    float* pDecc = symaddr(g_decc);
    float* pAttn = symaddr(g_attn);
    float* pCin = symaddr(g_cin);
    float* pConst = symaddr(g_const);
    float* pH1 = symaddr(g_h1);
    float* pH2 = symaddr(g_h2);

    cudaFuncSetAttribute(enc_tc_k, cudaFuncAttributeMaxDynamicSharedMemorySize, SMEM_ENC);
    cudaFuncSetAttribute(dec_persist_k, cudaFuncAttributeMaxDynamicSharedMemorySize, SMEM_DEC);

    dim3 tb(32, 8);
    wsplit_perm_k<<<(NG*EE + 255)/256, 256>>>(encWih0, EE, pWihHi, pWihLo);
    for (int l = 1; l < 4; l++)
        wsplit_perm_k<<<(NG*HH + 255)/256, 256>>>(encWihs + (size_t)(l-1)*NG*HH, HH,
                                                  pWihHi + NG*EE + (size_t)(l-1)*NG*HH,
                                                  pWihLo + NG*EE + (size_t)(l-1)*NG*HH);
    for (int l = 0; l < 4; l++)
        wsplit_perm_k<<<(NG*HH + 255)/256, 256>>>(encWhh + (size_t)l*NG*HH, HH,
                                                  pWhhHi + (size_t)l*NG*HH,
                                                  pWhhLo + (size_t)l*NG*HH);
    for (int l = 0; l < 4; l++)
        addv_perm_k<<<4, 256>>>(encBih + l*NG, encBhh + l*NG, pBiasEncP + l*NG);
    for (int l = 0; l < 3; l++)
        transpose_k<<<dim3(8, 32), tb>>>(decWihs + (size_t)l*NG*HH, HH, NG, HH, pDecWihsT + (size_t)l*KSZ, NG);
    for (int l = 1; l < 4; l++)
        transpose_k<<<dim3(8, 32), tb>>>(decWhh + (size_t)l*NG*HH, HH, NG, HH, pDecWhhT + (size_t)(l-1)*KSZ, NG);
    transpose_k<<<dim3(8, 32), tb>>>(decWhh, HH, NG, HH, pPack, NG);
    transpose_k<<<dim3(8, 32), tb>>>(decWih0, 384, NG, HH, pPack + (size_t)HH*NG, NG);
    transpose_k<<<dim3(4, 32), tb>>>(decWih0 + HH, 384, NG, EE, pWeT, NG);
    addv_k<<<16, 256>>>(decBih, decBhh, pBiasDec, 4*NG);

    emb_k<<<MTOT, 128>>>(x, encLinW, encLinB, pAhi, pAlo);

    for (int l = 0; l < 4; l++){
        const __nv_bfloat16* wh = (l == 0) ? pWihHi : (pWihHi + NG*EE + (size_t)(l-1)*NG*HH);
        const __nv_bfloat16* wl = (l == 0) ? pWihLo : (pWihLo + NG*EE + (size_t)(l-1)*NG*HH);
        int Kin = (l == 0) ? EE : HH;
        gemm_tc_k<<<dim3(8, MTOT/128), 256>>>(pAhi, pAlo, wh, wl, pBiasEncP + l*NG, pX, Kin);
        reset_barrier_k<<<1, 1>>>();
        enc_tc_k<<<88, 256, SMEM_ENC>>>(pX, pWhhHi + (size_t)l*NG*HH, pWhhLo + (size_t)l*NG*HH,
                                        pY, pC, pAhi, pAlo, (l == 3) ? 1 : 0);
        snap_k<<<64, 256>>>(pY + (size_t)(TT_-1)*GT*HH, pC, tord,
                            pDech + (size_t)l*BB*HH, pDecc + (size_t)l*BB*HH);
    }

    attn_k<<<BB, 256>>>(pY, attnW, pAttn);
    pack_cin_k<<<BB, 512>>>(pDech, pAttn, pCin);
    gemm_k<<<dim3(8, 1), 256>>>(pCin, pPack, pBiasDec, pConst, BB, NG, 512);
    for (int l = 1; l < 4; l++)
        gemm_k<<<dim3(8, 1), 256>>>(pDech + (size_t)l*BB*HH, pDecWhhT + (size_t)(l-1)*KSZ,
                                    pBiasDec + l*NG, pConst + (size_t)l*BB*NG, BB, NG, HH);

    reset_barrier_k<<<1, 1>>>();
    dec_persist_k<<<96, 256, SMEM_DEC>>>(x, tord, pConst, pDecc, pWeT, pDecWihsT,
                                         pH1, pH2, outW, outB, decEmbW, decEmbB, out);
}